// round 5
// baseline (speedup 1.0000x reference)
#include <cuda_runtime.h>

#define BATCH 2048
#define NNB   64
#define MM    10
#define FEAT  40
#define RMAX  (MM + 1)      // rhs columns (models + Kcross)
#define RPAD  12
#define PDS   65            // spdA row stride (conflict-free scalar)

__device__ float g_sig_partial[MM * BATCH];
__device__ unsigned int g_done = 0;

struct __align__(16) BlockSmem {
    float spdA[NNB][PDS];            // distances, then raw L
    union {
        float sxn[NNB][FEAT];        // phase 1: neighbor features (160B rows, f4-aligned)
        struct {
            float zs[NNB][13];       // forward-solve result (stride 13: conflict-free)
            float sYo[NNB][13];      // original rhs (for sigma)
            float srow[2][80];       // [0..63] pivot row, [64..75] rhs, [76] dv2
        } p2;
    } u;
    float sdinv[NNB];
    float scd[NNB];
    float snorm[NNB];
    float sKc[NNB];
    int   sidx[NNB];
    float sxb[FEAT];
    float gls[MM], geps[MM];
    int   gcnt[MM];
    int   gmem[MM][MM];
    int   ng;
    unsigned int ticket;
    float sred[4];
};

// pairwise distances for this thread's 32-column half (exactly symmetric:
// identical accumulation order on both sides; dup indices forced to 0)
__device__ __forceinline__ void dist32(BlockSmem* S, const float* xi,
                                       int i, int h, int myidx)
{
    const float ni = S->snorm[i];
    const int j0 = 32 * h;
    for (int jj = 0; jj < 32; jj++) {
        const int j = j0 + jj;
        const float4* vr = reinterpret_cast<const float4*>(S->u.sxn[j]);
        float d0 = 0.f, d1 = 0.f, d2 = 0.f, d3 = 0.f;
#pragma unroll
        for (int q = 0; q < FEAT / 4; q++) {
            float4 v = vr[q];
            d0 += xi[4*q+0] * v.x;
            d1 += xi[4*q+1] * v.y;
            d2 += xi[4*q+2] * v.z;
            d3 += xi[4*q+3] * v.w;
        }
        float dot = (d0 + d1) + (d2 + d3);
        float dd = ni + S->snorm[j] - 2.f * dot;
        if (S->sidx[j] == myidx) dd = 0.f;
        S->spdA[i][j] = (dd > 0.f) ? sqrtf(dd) : 0.f;
    }
}

__global__ void __launch_bounds__(128, 5)
muygps_main(const float* __restrict__ x,
            const float* __restrict__ ls,
            const float* __restrict__ eps,
            const int*   __restrict__ bidx,
            const int*   __restrict__ nidx,
            const float* __restrict__ Y,
            float*       __restrict__ out)
{
    extern __shared__ char smem_raw[];
    BlockSmem* S = reinterpret_cast<BlockSmem*>(smem_raw);
    const int tid = threadIdx.x;
    const int i   = tid & 63;        // row
    const int h   = tid >> 6;        // column half (warp-uniform)
    const int b   = blockIdx.x;

    if (tid < FEAT) S->sxb[tid] = x[(size_t)bidx[b] * FEAT + tid];

    if (tid == 0) {
        int ng = 0;
        for (int m = 0; m < MM; m++) {
            float lm = ls[m], em = eps[m];
            int g = -1;
            for (int q = 0; q < ng; q++)
                if (S->gls[q] == lm && S->geps[q] == em) { g = q; break; }
            if (g < 0) { g = ng++; S->gls[g] = lm; S->geps[g] = em; S->gcnt[g] = 0; }
            S->gmem[g][S->gcnt[g]++] = m;
        }
        S->ng = ng;
    }

    const int myidx = nidx[b * NNB + i];

    // ---- phase 1: each thread loads half of its row's features
    {
        const float4* xr = reinterpret_cast<const float4*>(x + (size_t)myidx * FEAT + 20 * h);
        float4* sx = reinterpret_cast<float4*>(&S->u.sxn[i][20 * h]);
#pragma unroll
        for (int q = 0; q < 5; q++) sx[q] = xr[q];
        if (h == 0) S->sidx[i] = myidx;
    }
    __syncthreads();

    {
        float xi[FEAT];
        const float4* sx = reinterpret_cast<const float4*>(S->u.sxn[i]);
        float nrm = 0.f;
#pragma unroll
        for (int q = 0; q < FEAT / 4; q++) {
            float4 v = sx[q];
            xi[4*q+0] = v.x; xi[4*q+1] = v.y; xi[4*q+2] = v.z; xi[4*q+3] = v.w;
            nrm += v.x*v.x + v.y*v.y + v.z*v.z + v.w*v.w;
        }
        if (h == 0) {
            S->snorm[i] = nrm;
            float d2 = 0.f;
#pragma unroll
            for (int f = 0; f < FEAT; f++) { float t = xi[f] - S->sxb[f]; d2 += t * t; }
            S->scd[i] = (d2 > 0.f) ? sqrtf(d2) : 0.f;
        }
        __syncthreads();
        dist32(S, xi, i, h, myidx);
    }
    __syncthreads();

    const float* Yrow = Y + ((size_t)b * NNB + i) * MM;
    const int ng = S->ng;

    float* srowA = S->u.p2.srow[0];
    float* srowB = S->u.p2.srow[1];

    for (int g = 0; g < ng; g++) {
        if (g > 0) {    // general case: union was overwritten; rebuild distances
            const float4* xr = reinterpret_cast<const float4*>(x + (size_t)myidx * FEAT + 20 * h);
            float4* sx = reinterpret_cast<float4*>(&S->u.sxn[i][20 * h]);
#pragma unroll
            for (int q = 0; q < 5; q++) sx[q] = xr[q];
            __syncthreads();
            float xi[FEAT];
            const float4* sxr = reinterpret_cast<const float4*>(S->u.sxn[i]);
#pragma unroll
            for (int q = 0; q < FEAT / 4; q++) {
                float4 v = sxr[q];
                xi[4*q+0] = v.x; xi[4*q+1] = v.y; xi[4*q+2] = v.z; xi[4*q+3] = v.w;
            }
            dist32(S, xi, i, h, myidx);
            __syncthreads();
        }
        const float inv_ls = 1.0f / S->gls[g];
        const float epg    = S->geps[g];
        const int   nm     = S->gcnt[g];
        const int   R      = nm + 1;

        // ---- build this thread's 32-column slice of Kp
        float a[32];
        {
            const float* pd = &S->spdA[i][32 * h];
#pragma unroll
            for (int c = 0; c < 32; c++)
                a[c] = __expf(-pd[c] * inv_ls);
            if (h == (i >> 5)) a[i & 31] += epg;
        }

        // ---- rhs registers (h==0 only)
        float rr[RPAD];
        if (h == 0) {
            float Kc = __expf(-S->scd[i] * inv_ls);
            S->sKc[i] = Kc;
#pragma unroll
            for (int r = 0; r < RPAD; r++) rr[r] = 0.f;
#pragma unroll
            for (int r = 0; r < MM; r++)
                if (r < nm) rr[r] = Yrow[S->gmem[g][r]];
#pragma unroll
            for (int r = 0; r < RMAX; r++)
                if (r == nm) rr[r] = Kc;
#pragma unroll
            for (int r = 0; r < RMAX; r++) S->u.p2.sYo[i][r] = rr[r];
        }

        // ---- bootstrap publish: pivot row 0 (zero-masked at/below diag) + rhs + dv2
        if (h == 0) {
            srowA[i] = (i > 0) ? a[0] : 0.f;
            if (i == 0) {
                float dv = rsqrtf(a[0]);
                S->sdinv[0] = dv;
                srowA[76] = dv * dv;
                float4* wR = reinterpret_cast<float4*>(srowA + 64);
                wR[0] = make_float4(rr[0], rr[1], rr[2],  rr[3]);
                wR[1] = make_float4(rr[4], rr[5], rr[6],  rr[7]);
                wR[2] = make_float4(rr[8], rr[9], rr[10], rr[11]);
            }
        }

        // ---- Cholesky + fused forward solve; t comes from the broadcast row
        //      itself (symmetry: srow[i] == A[i][k]); one barrier per step.
#pragma unroll
        for (int k = 0; k < NNB - 1; k++) {
            __syncthreads();
            const float* rbS = (k & 1) ? srowB : srowA;
            float*       wbS = (k & 1) ? srowA : srowB;
            const float dv2 = rbS[76];
            const float t   = rbS[i] * dv2;          // zero for i<=k
            if (i > k) {
                if (h == 0) {
                    if (k < 31) {
                        const float4* r4 = reinterpret_cast<const float4*>(rbS);
#pragma unroll
                        for (int q = (k + 1) >> 2; q < 8; q++) {
                            float4 v = r4[q];
                            a[4*q+0] -= t * v.x;
                            a[4*q+1] -= t * v.y;
                            a[4*q+2] -= t * v.z;
                            a[4*q+3] -= t * v.w;
                        }
                    }
                    const float4* rR = reinterpret_cast<const float4*>(rbS + 64);
#pragma unroll
                    for (int c = 0; c < 3; c++) {
                        float4 v = rR[c];
                        rr[4*c+0] -= t * v.x;
                        rr[4*c+1] -= t * v.y;
                        rr[4*c+2] -= t * v.z;
                        rr[4*c+3] -= t * v.w;
                    }
                } else {
                    const float4* r4 = reinterpret_cast<const float4*>(rbS + 32);
#pragma unroll
                    for (int q = (k < 32) ? 0 : ((k - 31) >> 2); q < 8; q++) {
                        float4 v = r4[q];
                        a[4*q+0] -= t * v.x;
                        a[4*q+1] -= t * v.y;
                        a[4*q+2] -= t * v.z;
                        a[4*q+3] -= t * v.w;
                    }
                }
            }
            // cooperative publish of pivot row k+1 (zero-masked j<=k+1)
            {
                const int P = k + 1;
                if (h == (P >> 5))
                    wbS[i] = (i > P) ? a[P & 31] : 0.f;
                if (i == P) {
                    if (h == (P >> 5)) {
                        float dv = rsqrtf(a[P & 31]);
                        S->sdinv[P] = dv;
                        wbS[76] = dv * dv;
                    }
                    if (h == 0) {
                        float4* wR = reinterpret_cast<float4*>(wbS + 64);
                        wR[0] = make_float4(rr[0], rr[1], rr[2],  rr[3]);
                        wR[1] = make_float4(rr[4], rr[5], rr[6],  rr[7]);
                        wR[2] = make_float4(rr[8], rr[9], rr[10], rr[11]);
                    }
                }
            }
        }

        // ---- dump raw L slice; wait for all sdinv; store z
        {
            float* Lp = &S->spdA[i][32 * h];
#pragma unroll
            for (int c = 0; c < 32; c++) Lp[c] = a[c];
        }
        __syncthreads();
        if (h == 0) {
            float dvi = S->sdinv[i];
#pragma unroll
            for (int r = 0; r < RMAX; r++) S->u.p2.zs[i][r] = rr[r] * dvi;
        }
        __syncthreads();

        // ---- backward solve (L^T f = z): 4 warps x 3 RHS, zero barriers
        {
            const int wd    = tid >> 5;
            const int lane  = tid & 31;
            const int rbase = 3 * wd;

            float accL[3], accH[3], pred[3], sig[3], fk[3];
#pragma unroll
            for (int r = 0; r < 3; r++) { accL[r]=0.f; accH[r]=0.f; pred[r]=0.f; sig[r]=0.f; }

#pragma unroll
            for (int kk = 0; kk < NNB; kk++) {
                const int k = NNB - 1 - kk;
                const float dv = S->sdinv[k];
#pragma unroll
                for (int r = 0; r < 3; r++) {
                    int rq = rbase + r; if (rq >= RMAX) rq = 0;
                    float accv = (k >= 32) ? accH[r] : accL[r];
                    fk[r] = (S->u.p2.zs[k][rq] - dv * accv) * dv;
                }
#pragma unroll
                for (int r = 0; r < 3; r++)
                    fk[r] = __shfl_sync(0xffffffffu, fk[r], k & 31);

                float rowL = S->spdA[k][lane];
                if (lane < k) {
#pragma unroll
                    for (int r = 0; r < 3; r++) accL[r] += rowL * fk[r];
                }
                if (k > 32) {
                    float rowH = S->spdA[k][lane + 32];
                    if (lane + 32 < k) {
#pragma unroll
                        for (int r = 0; r < 3; r++) accH[r] += rowH * fk[r];
                    }
                }
                if (lane == 0) {
                    float kc = S->sKc[k];
#pragma unroll
                    for (int r = 0; r < 3; r++) {
                        int rq = rbase + r; if (rq >= RMAX) rq = 0;
                        pred[r] += kc * fk[r];
                        sig[r]  += S->u.p2.sYo[k][rq] * fk[r];
                    }
                }
            }

            if (lane == 0) {
#pragma unroll
                for (int r = 0; r < 3; r++) {
                    int rg = rbase + r;
                    if (rg < R) {
                        if (rg < nm) {
                            int m = S->gmem[g][rg];
                            out[b * MM + m]              = pred[r];
                            g_sig_partial[m * BATCH + b] = sig[r];
                        } else {           // rg == nm -> shared variance column
                            float var = 1.0f - pred[r];
                            for (int q = 0; q < nm; q++)
                                out[BATCH * MM + b * MM + S->gmem[g][q]] = var;
                        }
                    }
                }
            }
        }
        __syncthreads();
    }

    // ---- last-block sigma reduction (deterministic fixed-order sum)
    __threadfence();
    __syncthreads();
    if (tid == 0) S->ticket = atomicAdd(&g_done, 1u);
    __syncthreads();
    if (S->ticket == gridDim.x - 1) {
        __threadfence();
        const int lane = tid & 31, w = tid >> 5;
        for (int m = 0; m < MM; m++) {
            float s = 0.f;
            for (int t = tid; t < BATCH; t += 128)
                s += g_sig_partial[m * BATCH + t];
#pragma unroll
            for (int off = 16; off > 0; off >>= 1)
                s += __shfl_down_sync(0xffffffffu, s, off);
            if (lane == 0) S->sred[w] = s;
            __syncthreads();
            if (tid == 0) {
                float tot = S->sred[0] + S->sred[1] + S->sred[2] + S->sred[3];
                out[2 * BATCH * MM + m] = tot / (float)(BATCH * NNB);
            }
            __syncthreads();
        }
        if (tid == 0) g_done = 0;    // reset for next graph replay
    }
}

extern "C" void kernel_launch(void* const* d_in, const int* in_sizes, int n_in,
                              void* d_out, int out_size)
{
    const float* x    = (const float*)d_in[0];
    const float* ls   = (const float*)d_in[1];
    const float* eps  = (const float*)d_in[2];
    const int*   bidx = (const int*)d_in[3];
    const int*   nidx = (const int*)d_in[4];
    const float* Y    = (const float*)d_in[5];
    float* out = (float*)d_out;

    cudaFuncSetAttribute(muygps_main, cudaFuncAttributeMaxDynamicSharedMemorySize,
                         (int)sizeof(BlockSmem));
    muygps_main<<<BATCH, 128, sizeof(BlockSmem)>>>(x, ls, eps, bidx, nidx, Y, out);
}

// round 6
// speedup vs baseline: 1.0571x; 1.0571x over previous
#include <cuda_runtime.h>

#define BATCH 2048
#define NNB   64
#define MM    10
#define FEAT  40
#define RMAX  (MM + 1)      // max rhs columns (models + 1 Kcross)
#define RPAD  12

__device__ float g_sig_partial[MM * BATCH];
__device__ unsigned int g_done = 0;

// per-element named barrier: 64 threads (2 warps), ids 1,2
#define EBAR(id) asm volatile("bar.sync %0, 64;" :: "r"(id) : "memory")

struct __align__(16) ElemSmem {
    float spdA[NNB][NNB + 1];        // distances, then raw L
    union {
        float sxn[NNB][FEAT];        // phase 1: neighbor features
        struct {
            float zs[NNB][RPAD];     // forward-solve result
            float sYo[NNB][RPAD];    // original rhs (for sigma)
            float srow[2][80];       // [0..63] bcast column, [64..75] rhs, [76] dv2
        } p2;
    } u;
    float sdinv[NNB];
    float scd[NNB];
    float snorm[NNB];
    float sKc[NNB];
    int   sidx[NNB];
    float sxb[FEAT];
};

struct BlockSmem {
    ElemSmem e[2];
    float gls[MM], geps[MM];
    int   gcnt[MM];
    int   gmem[MM][MM];
    int   ng;
    unsigned int ticket;
    float sred[4];
};

// pairwise distances from sxn (phase 1 and ng>1 rebuild)
__device__ __forceinline__ void dist_from_sxn(ElemSmem* E, const float* xi,
                                              int i, int myidx)
{
    const float ni = E->snorm[i];
    for (int j = 0; j < NNB; j++) {
        const float4* vr = reinterpret_cast<const float4*>(E->u.sxn[j]);
        float d0 = 0.f, d1 = 0.f, d2 = 0.f, d3 = 0.f;
#pragma unroll
        for (int q = 0; q < FEAT / 4; q++) {
            float4 v = vr[q];
            d0 += xi[4*q+0] * v.x;
            d1 += xi[4*q+1] * v.y;
            d2 += xi[4*q+2] * v.z;
            d3 += xi[4*q+3] * v.w;
        }
        float dot = (d0 + d1) + (d2 + d3);
        float dd = ni + E->snorm[j] - 2.f * dot;
        if (E->sidx[j] == myidx) dd = 0.f;
        E->spdA[i][j] = (dd > 0.f) ? sqrtf(dd) : 0.f;
    }
}

__global__ void __launch_bounds__(128, 3)
muygps_main(const float* __restrict__ x,
            const float* __restrict__ ls,
            const float* __restrict__ eps,
            const int*   __restrict__ bidx,
            const int*   __restrict__ nidx,
            const float* __restrict__ Y,
            float*       __restrict__ out)
{
    extern __shared__ char smem_raw[];
    BlockSmem* S = reinterpret_cast<BlockSmem*>(smem_raw);
    const int tid  = threadIdx.x;
    const int e    = tid >> 6;
    const int i    = tid & 63;
    const int barid = 1 + e;
    const int b    = blockIdx.x * 2 + e;
    ElemSmem* E = &S->e[e];

    if (i < FEAT) E->sxb[i] = x[(size_t)bidx[b] * FEAT + i];

    if (tid == 0) {
        int ng = 0;
        for (int m = 0; m < MM; m++) {
            float lm = ls[m], em = eps[m];
            int g = -1;
            for (int q = 0; q < ng; q++)
                if (S->gls[q] == lm && S->geps[q] == em) { g = q; break; }
            if (g < 0) { g = ng++; S->gls[g] = lm; S->geps[g] = em; S->gcnt[g] = 0; }
            S->gmem[g][S->gcnt[g]++] = m;
        }
        S->ng = ng;
    }

    const int myidx = nidx[b * NNB + i];

    // ---- phase 1: gather features, norms, distances (xi scoped)
    {
        float xi[FEAT];
        const float4* xr = reinterpret_cast<const float4*>(x + (size_t)myidx * FEAT);
        float4* sx = reinterpret_cast<float4*>(E->u.sxn[i]);
        float nrm = 0.f;
#pragma unroll
        for (int q = 0; q < FEAT / 4; q++) {
            float4 v = xr[q];
            sx[q] = v;
            xi[4*q+0] = v.x; xi[4*q+1] = v.y; xi[4*q+2] = v.z; xi[4*q+3] = v.w;
            nrm += v.x*v.x + v.y*v.y + v.z*v.z + v.w*v.w;
        }
        E->snorm[i] = nrm;
        E->sidx[i]  = myidx;
        __syncthreads();                 // covers group table + both elements

        float d2 = 0.f;
#pragma unroll
        for (int f = 0; f < FEAT; f++) { float t = xi[f] - E->sxb[f]; d2 += t * t; }
        E->scd[i] = (d2 > 0.f) ? sqrtf(d2) : 0.f;

        dist_from_sxn(E, xi, i, myidx);
    }
    EBAR(barid);

    const float* Yrow = Y + ((size_t)b * NNB + i) * MM;
    const int ng = S->ng;

    for (int g = 0; g < ng; g++) {
        if (g > 0) {   // general case: union overwritten -> re-gather, rebuild
            float xi[FEAT];
            const float4* xr = reinterpret_cast<const float4*>(x + (size_t)myidx * FEAT);
            float4* sx = reinterpret_cast<float4*>(E->u.sxn[i]);
#pragma unroll
            for (int q = 0; q < FEAT / 4; q++) {
                float4 v = xr[q];
                sx[q] = v;
                xi[4*q+0] = v.x; xi[4*q+1] = v.y; xi[4*q+2] = v.z; xi[4*q+3] = v.w;
            }
            EBAR(barid);
            dist_from_sxn(E, xi, i, myidx);
            EBAR(barid);
        }
        const float inv_ls = 1.0f / S->gls[g];
        const float epg    = S->geps[g];
        const int   nm     = S->gcnt[g];
        const int   R      = nm + 1;

        float* srowA = E->u.p2.srow[0];
        float* srowB = E->u.p2.srow[1];

        // ---- register row of Kp (full symmetric row)
        float a[NNB];
#pragma unroll
        for (int j = 0; j < NNB; j++) {
            float v = __expf(-E->spdA[i][j] * inv_ls);
            a[j] = (j == i) ? v + epg : v;
        }
        const float Kc = __expf(-E->scd[i] * inv_ls);
        E->sKc[i] = Kc;

        // ---- rhs registers
        float rr[RPAD];
#pragma unroll
        for (int r = 0; r < RPAD; r++) rr[r] = 0.f;
#pragma unroll
        for (int r = 0; r < MM; r++)
            if (r < nm) rr[r] = Yrow[S->gmem[g][r]];
#pragma unroll
        for (int r = 0; r < RMAX; r++)
            if (r == nm) rr[r] = Kc;
#pragma unroll
        for (int r = 0; r < RMAX; r++) E->u.p2.sYo[i][r] = rr[r];

        // ---- bootstrap: cooperative publish of column 0 + thread0's dv2/rhs
        srowA[i] = (i > 0) ? a[0] : 0.f;
        if (i == 0) {
            float dv = rsqrtf(a[0]);
            E->sdinv[0] = dv;
            srowA[76] = dv * dv;
            float4* wR = reinterpret_cast<float4*>(srowA + 64);
            wR[0] = make_float4(rr[0], rr[1], rr[2],  rr[3]);
            wR[1] = make_float4(rr[4], rr[5], rr[6],  rr[7]);
            wR[2] = make_float4(rr[8], rr[9], rr[10], rr[11]);
        }

        // ---- Cholesky + fused forward solve; one named barrier per step.
        //      Broadcast data = column k (each thread's own a[k]) by symmetry;
        //      publish is ONE scalar STS per thread (no serial pivot publish).
#pragma unroll
        for (int k = 0; k < NNB - 1; k++) {
            EBAR(barid);
            const float* rbS = (k & 1) ? srowB : srowA;
            float*       wbS = (k & 1) ? srowA : srowB;
            const float dv2 = rbS[76];
            const float t   = a[k] * dv2;        // own register multiplier
            if (i > k) {
                const float4* r4 = reinterpret_cast<const float4*>(rbS);
                const int c0 = (k + 1) >> 2;     // rbS[j]=0 for j<=k: chunk-safe
#pragma unroll
                for (int c = c0; c < 16; c++) {
                    float4 v = r4[c];
                    a[4*c+0] -= t * v.x;
                    a[4*c+1] -= t * v.y;
                    a[4*c+2] -= t * v.z;
                    a[4*c+3] -= t * v.w;
                }
                const float4* rR = reinterpret_cast<const float4*>(rbS + 64);
#pragma unroll
                for (int c = 0; c < 3; c++) {
                    float4 v = rR[c];
                    rr[4*c+0] -= t * v.x;
                    rr[4*c+1] -= t * v.y;
                    rr[4*c+2] -= t * v.z;
                    rr[4*c+3] -= t * v.w;
                }
                if (i == k + 1) {                // new pivot: dv2 + rhs publish
                    float dv = rsqrtf(a[k + 1]);
                    E->sdinv[k + 1] = dv;
                    wbS[76] = dv * dv;
                    float4* wR = reinterpret_cast<float4*>(wbS + 64);
                    wR[0] = make_float4(rr[0], rr[1], rr[2],  rr[3]);
                    wR[1] = make_float4(rr[4], rr[5], rr[6],  rr[7]);
                    wR[2] = make_float4(rr[8], rr[9], rr[10], rr[11]);
                }
            }
            // cooperative column publish (zero-masked at/below new pivot)
            wbS[i] = (i > k + 1) ? a[k + 1] : 0.f;
        }

        // ---- dump raw L rows; store z (forward result)
#pragma unroll
        for (int j = 0; j < NNB; j++) E->spdA[i][j] = a[j];
        {
            float dvi = E->sdinv[i];
#pragma unroll
            for (int r = 0; r < RMAX; r++) E->u.p2.zs[i][r] = rr[r] * dvi;
        }
        EBAR(barid);

        // ---- warp-local backward solve (zero barriers), RHS split across 2 warps
        {
            const int wsub  = (tid >> 5) & 1;
            const int lane  = tid & 31;
            const int RHs   = (R + 1) >> 1;
            const int rbase = wsub ? RHs : 0;
            const int rend  = wsub ? R   : RHs;

            float accL[6], accH[6], pred[6], sig[6], fk[6];
#pragma unroll
            for (int r = 0; r < 6; r++) { accL[r]=0.f; accH[r]=0.f; pred[r]=0.f; sig[r]=0.f; }

#pragma unroll
            for (int kk = 0; kk < NNB; kk++) {
                const int k = NNB - 1 - kk;
                const float dv = E->sdinv[k];
#pragma unroll
                for (int r = 0; r < 6; r++) {
                    int rq = rbase + r; if (rq >= RMAX) rq = 0;
                    float accv = (k >= 32) ? accH[r] : accL[r];
                    fk[r] = (E->u.p2.zs[k][rq] - dv * accv) * dv;
                }
#pragma unroll
                for (int r = 0; r < 6; r++)
                    fk[r] = __shfl_sync(0xffffffffu, fk[r], k & 31);

                float rowL = E->spdA[k][lane];
                if (lane < k) {
#pragma unroll
                    for (int r = 0; r < 6; r++) accL[r] += rowL * fk[r];
                }
                if (k > 32) {
                    float rowH = E->spdA[k][lane + 32];
                    if (lane + 32 < k) {
#pragma unroll
                        for (int r = 0; r < 6; r++) accH[r] += rowH * fk[r];
                    }
                }
                if (lane == 0) {
                    float kc = E->sKc[k];
#pragma unroll
                    for (int r = 0; r < 6; r++) {
                        int rq = rbase + r; if (rq >= RMAX) rq = 0;
                        pred[r] += kc * fk[r];
                        sig[r]  += E->u.p2.sYo[k][rq] * fk[r];
                    }
                }
            }

            if (lane == 0) {
#pragma unroll
                for (int r = 0; r < 6; r++) {
                    int rg = rbase + r;
                    if (rg < rend) {
                        if (rg < nm) {
                            int m = S->gmem[g][rg];
                            out[b * MM + m]              = pred[r];
                            g_sig_partial[m * BATCH + b] = sig[r];
                        } else {
                            float var = 1.0f - pred[r];
                            for (int q = 0; q < nm; q++)
                                out[BATCH * MM + b * MM + S->gmem[g][q]] = var;
                        }
                    }
                }
            }
        }
        EBAR(barid);
    }

    // ---- last-block sigma reduction (deterministic fixed-order sum)
    __threadfence();
    __syncthreads();
    if (tid == 0) S->ticket = atomicAdd(&g_done, 1u);
    __syncthreads();
    if (S->ticket == gridDim.x - 1) {
        __threadfence();
        const int lane = tid & 31, w = tid >> 5;
        for (int m = 0; m < MM; m++) {
            float s = 0.f;
            for (int t = tid; t < BATCH; t += 128)
                s += g_sig_partial[m * BATCH + t];
#pragma unroll
            for (int off = 16; off > 0; off >>= 1)
                s += __shfl_down_sync(0xffffffffu, s, off);
            if (lane == 0) S->sred[w] = s;
            __syncthreads();
            if (tid == 0) {
                float tot = S->sred[0] + S->sred[1] + S->sred[2] + S->sred[3];
                out[2 * BATCH * MM + m] = tot / (float)(BATCH * NNB);
            }
            __syncthreads();
        }
        if (tid == 0) g_done = 0;        // reset for next graph replay
    }
}

extern "C" void kernel_launch(void* const* d_in, const int* in_sizes, int n_in,
                              void* d_out, int out_size)
{
    const float* x    = (const float*)d_in[0];
    const float* ls   = (const float*)d_in[1];
    const float* eps  = (const float*)d_in[2];
    const int*   bidx = (const int*)d_in[3];
    const int*   nidx = (const int*)d_in[4];
    const float* Y    = (const float*)d_in[5];
    float* out = (float*)d_out;

    cudaFuncSetAttribute(muygps_main, cudaFuncAttributeMaxDynamicSharedMemorySize,
                         (int)sizeof(BlockSmem));
    muygps_main<<<BATCH / 2, 128, sizeof(BlockSmem)>>>(x, ls, eps, bidx, nidx, Y, out);
}

// round 8
// speedup vs baseline: 1.6989x; 1.6071x over previous
#include <cuda_runtime.h>

#define BATCH 2048
#define NNB   64
#define MM    10
#define FEAT  40
#define RMAX  (MM + 1)      // rhs columns (models + Kcross)
#define RPAD  12

__device__ float g_sig_partial[MM * BATCH];
__device__ unsigned int g_done = 0;

// per-element named barrier: 64 threads (2 warps), ids 1,2
#define EBAR(id) asm volatile("bar.sync %0, 64;" :: "r"(id) : "memory")

struct __align__(16) ElemSmem {
    float spdA[NNB][NNB + 1];            // dot-acc -> distances -> raw L
    union {
        struct {                          // phase 1 (two feature tiles of 20)
            float sxn[NNB][20];
            float sxb[24];
            float snorm[NNB];
            int   sidx[NNB];
        } p1;
        struct {                          // phase 2
            float zs[NNB][RPAD];          // forward-solve result
            float sYo[NNB][RPAD];         // original rhs (for sigma)
            float srow[2][176];           // [0..63] colA, [64..127] colB,
                                          // [128..139] rhsA, [144..155] rhsB, [160] dv2a
        } p2;
    } u;
    float sdinv[NNB];
    float scd[NNB];
    float sKc[NNB];
};

struct BlockSmem {
    ElemSmem e[2];
    float gls[MM], geps[MM];
    int   gcnt[MM];
    int   gmem[MM][MM];
    int   ng;
    unsigned int ticket;
    float sred[4];
};

// two-tile distance builder: dots accumulated in spdA, then finalized.
// xb != nullptr also computes crosswise distances into scd.
__device__ __forceinline__ void build_dist(ElemSmem* E, const float* __restrict__ x,
                                           const float* __restrict__ xb,
                                           int i, int myidx, int barid)
{
    float nrm = 0.f, cd = 0.f;
#pragma unroll
    for (int t = 0; t < 2; t++) {
        float xi[20];
        {
            const float4* xr = reinterpret_cast<const float4*>(x + (size_t)myidx * FEAT + 20 * t);
            float4* sx = reinterpret_cast<float4*>(E->u.p1.sxn[i]);
#pragma unroll
            for (int q = 0; q < 5; q++) {
                float4 v = xr[q];
                sx[q] = v;
                xi[4*q+0]=v.x; xi[4*q+1]=v.y; xi[4*q+2]=v.z; xi[4*q+3]=v.w;
                nrm += v.x*v.x + v.y*v.y + v.z*v.z + v.w*v.w;
            }
        }
        if (xb != nullptr && i < 20) E->u.p1.sxb[i] = xb[20 * t + i];
        if (t == 0) E->u.p1.sidx[i] = myidx;
        EBAR(barid);
        if (xb != nullptr) {
#pragma unroll
            for (int f = 0; f < 20; f++) { float d = xi[f] - E->u.p1.sxb[f]; cd += d * d; }
        }
        for (int j = 0; j < NNB; j++) {
            const float4* vr = reinterpret_cast<const float4*>(E->u.p1.sxn[j]);
            float d0=0.f,d1=0.f,d2=0.f,d3=0.f;
#pragma unroll
            for (int q = 0; q < 5; q++) {
                float4 v = vr[q];
                d0 += xi[4*q+0]*v.x; d1 += xi[4*q+1]*v.y;
                d2 += xi[4*q+2]*v.z; d3 += xi[4*q+3]*v.w;
            }
            float dot = (d0+d1)+(d2+d3);
            if (t == 0) E->spdA[i][j] = dot;
            else        E->spdA[i][j] += dot;
        }
        EBAR(barid);
    }
    E->u.p1.snorm[i] = nrm;
    if (xb != nullptr) E->scd[i] = (cd > 0.f) ? sqrtf(cd) : 0.f;
    EBAR(barid);
    const float ni = nrm;
    for (int j = 0; j < NNB; j++) {
        float dd = ni + E->u.p1.snorm[j] - 2.f * E->spdA[i][j];
        if (E->u.p1.sidx[j] == myidx) dd = 0.f;
        E->spdA[i][j] = (dd > 0.f) ? sqrtf(dd) : 0.f;
    }
    EBAR(barid);
}

__global__ void __launch_bounds__(128, 4)
muygps_main(const float* __restrict__ x,
            const float* __restrict__ ls,
            const float* __restrict__ eps,
            const int*   __restrict__ bidx,
            const int*   __restrict__ nidx,
            const float* __restrict__ Y,
            float*       __restrict__ out)
{
    extern __shared__ char smem_raw[];
    BlockSmem* S = reinterpret_cast<BlockSmem*>(smem_raw);
    const int tid   = threadIdx.x;
    const int e     = tid >> 6;
    const int i     = tid & 63;
    const int barid = 1 + e;
    const int b     = blockIdx.x * 2 + e;
    ElemSmem* E = &S->e[e];

    if (tid == 0) {
        int ng = 0;
        for (int m = 0; m < MM; m++) {
            float lm = ls[m], em = eps[m];
            int g = -1;
            for (int q = 0; q < ng; q++)
                if (S->gls[q] == lm && S->geps[q] == em) { g = q; break; }
            if (g < 0) { g = ng++; S->gls[g] = lm; S->geps[g] = em; S->gcnt[g] = 0; }
            S->gmem[g][S->gcnt[g]++] = m;
        }
        S->ng = ng;
    }

    const int myidx = nidx[b * NNB + i];
    const float* xb = x + (size_t)bidx[b] * FEAT;

    build_dist(E, x, xb, i, myidx, barid);
    __syncthreads();                       // group table visibility

    const float* Yrow = Y + ((size_t)b * NNB + i) * MM;
    const int ng = S->ng;

    for (int g = 0; g < ng; g++) {
        if (g > 0)                          // union overwritten: rebuild distances
            build_dist(E, x, nullptr, i, myidx, barid);

        const float inv_ls = 1.0f / S->gls[g];
        const float epg    = S->geps[g];
        const int   nm     = S->gcnt[g];
        const int   R      = nm + 1;

        float* srowA = E->u.p2.srow[0];
        float* srowB = E->u.p2.srow[1];

        // ---- register row of Kp
        float a[NNB];
#pragma unroll
        for (int j = 0; j < NNB; j++) {
            float v = __expf(-E->spdA[i][j] * inv_ls);
            a[j] = (j == i) ? v + epg : v;
        }
        const float Kc = __expf(-E->scd[i] * inv_ls);
        E->sKc[i] = Kc;

        // ---- rhs registers
        float rr[RPAD];
#pragma unroll
        for (int r = 0; r < RPAD; r++) rr[r] = 0.f;
#pragma unroll
        for (int r = 0; r < MM; r++)
            if (r < nm) rr[r] = Yrow[S->gmem[g][r]];
#pragma unroll
        for (int r = 0; r < RMAX; r++)
            if (r == nm) rr[r] = Kc;
#pragma unroll
        for (int r = 0; r < RMAX; r++) E->u.p2.sYo[i][r] = rr[r];

        float mydv = 0.f;

        // ---- bootstrap: row 0 (colA: diag zeroed, dv2 separate) and
        //      row 1 (colB: DIAG KEPT — consumers need it for diagB)
        if (i == 0) {
            float dv = rsqrtf(a[0]);
            mydv = dv;
            E->sdinv[0] = dv;
            srowA[160] = dv * dv;
            float4* w4 = reinterpret_cast<float4*>(srowA);
            w4[0] = make_float4(0.f, a[1], a[2], a[3]);
#pragma unroll
            for (int c = 1; c < 16; c++)
                w4[c] = make_float4(a[4*c+0], a[4*c+1], a[4*c+2], a[4*c+3]);
            float4* wA = reinterpret_cast<float4*>(srowA + 128);
            wA[0] = make_float4(rr[0], rr[1], rr[2],  rr[3]);
            wA[1] = make_float4(rr[4], rr[5], rr[6],  rr[7]);
            wA[2] = make_float4(rr[8], rr[9], rr[10], rr[11]);
        }
        if (i == 1) {
            float4* w4 = reinterpret_cast<float4*>(srowA + 64);
            w4[0] = make_float4(0.f, a[1], a[2], a[3]);   // keep diag a[1]
#pragma unroll
            for (int c = 1; c < 16; c++)
                w4[c] = make_float4(a[4*c+0], a[4*c+1], a[4*c+2], a[4*c+3]);
            float4* wB = reinterpret_cast<float4*>(srowA + 144);
            wB[0] = make_float4(rr[0], rr[1], rr[2],  rr[3]);
            wB[1] = make_float4(rr[4], rr[5], rr[6],  rr[7]);
            wB[2] = make_float4(rr[8], rr[9], rr[10], rr[11]);
        }

        // ---- double-step Cholesky + fused forward solve: 32 barriers total.
#pragma unroll
        for (int K = 0; K < NNB; K += 2) {
            EBAR(barid);
            const float* rbS = ((K >> 1) & 1) ? srowB : srowA;
            float*       wbS = ((K >> 1) & 1) ? srowA : srowB;

            const float dv2a  = rbS[160];
            const float cak1  = rbS[K + 1];
            const float cbk1  = rbS[64 + K + 1];     // row K+1 diagonal (kept)
            const float cc    = cak1 * dv2a;
            const float diagB = cbk1 - cc * cak1;
            const float sdb   = rsqrtf(diagB);
            const float dv2b  = sdb * sdb;
            const float t1    = a[K] * dv2a;
            const float t2    = (a[K + 1] - t1 * cak1) * dv2b;

            if (i == K + 1) {
                mydv = sdb;
                E->sdinv[K + 1] = sdb;
                const float4* rA4 = reinterpret_cast<const float4*>(rbS + 128);
#pragma unroll
                for (int c = 0; c < 3; c++) {
                    float4 va = rA4[c];
                    rr[4*c+0] -= t1 * va.x; rr[4*c+1] -= t1 * va.y;
                    rr[4*c+2] -= t1 * va.z; rr[4*c+3] -= t1 * va.w;
                }
            }
            if (K < NNB - 2 && i >= K + 2) {
                const float4* r4a = reinterpret_cast<const float4*>(rbS);
                const float4* r4b = reinterpret_cast<const float4*>(rbS + 64);
                const int c0 = (K + 2) >> 2;
                {   // boundary chunk: t2 term masked for j <= K+1 (compile-time)
                    float4 va = r4a[c0], vb = r4b[c0];
                    float b0 = (4*c0+0 > K+1) ? (vb.x - cc * va.x) : 0.f;
                    float b1 = (4*c0+1 > K+1) ? (vb.y - cc * va.y) : 0.f;
                    float b2 = (4*c0+2 > K+1) ? (vb.z - cc * va.z) : 0.f;
                    float b3 = (4*c0+3 > K+1) ? (vb.w - cc * va.w) : 0.f;
                    a[4*c0+0] -= t1 * va.x; a[4*c0+0] -= t2 * b0;
                    a[4*c0+1] -= t1 * va.y; a[4*c0+1] -= t2 * b1;
                    a[4*c0+2] -= t1 * va.z; a[4*c0+2] -= t2 * b2;
                    a[4*c0+3] -= t1 * va.w; a[4*c0+3] -= t2 * b3;
                }
#pragma unroll
                for (int c = c0 + 1; c < 16; c++) {
                    float4 va = r4a[c], vb = r4b[c];
                    a[4*c+0] -= t1 * va.x; a[4*c+0] -= t2 * (vb.x - cc * va.x);
                    a[4*c+1] -= t1 * va.y; a[4*c+1] -= t2 * (vb.y - cc * va.y);
                    a[4*c+2] -= t1 * va.z; a[4*c+2] -= t2 * (vb.z - cc * va.z);
                    a[4*c+3] -= t1 * va.w; a[4*c+3] -= t2 * (vb.w - cc * va.w);
                }
                const float4* rA4 = reinterpret_cast<const float4*>(rbS + 128);
                const float4* rB4 = reinterpret_cast<const float4*>(rbS + 144);
#pragma unroll
                for (int c = 0; c < 3; c++) {
                    float4 va = rA4[c], vb = rB4[c];
                    rr[4*c+0] -= t1 * va.x; rr[4*c+0] -= t2 * (vb.x - cc * va.x);
                    rr[4*c+1] -= t1 * va.y; rr[4*c+1] -= t2 * (vb.y - cc * va.y);
                    rr[4*c+2] -= t1 * va.z; rr[4*c+2] -= t2 * (vb.z - cc * va.z);
                    rr[4*c+3] -= t1 * va.w; rr[4*c+3] -= t2 * (vb.w - cc * va.w);
                }

                // publishes for next interval (pivot-style)
                if (i == K + 2) {
                    float dv = rsqrtf(a[K + 2]);
                    mydv = dv;
                    E->sdinv[K + 2] = dv;
                    wbS[160] = dv * dv;
                    const int cp = (K + 2) >> 2;
                    float4* w4 = reinterpret_cast<float4*>(wbS);
                    {   // colA: zero j <= K+2 (diag via dv2), keep j >= K+3
                        float4 v;
                        v.x = (4*cp+0 > K+2) ? a[4*cp+0] : 0.f;
                        v.y = (4*cp+1 > K+2) ? a[4*cp+1] : 0.f;
                        v.z = (4*cp+2 > K+2) ? a[4*cp+2] : 0.f;
                        v.w = (4*cp+3 > K+2) ? a[4*cp+3] : 0.f;
                        w4[cp] = v;
                    }
#pragma unroll
                    for (int c = cp + 1; c < 16; c++)
                        w4[c] = make_float4(a[4*c+0], a[4*c+1], a[4*c+2], a[4*c+3]);
                    float4* wA = reinterpret_cast<float4*>(wbS + 128);
                    wA[0] = make_float4(rr[0], rr[1], rr[2],  rr[3]);
                    wA[1] = make_float4(rr[4], rr[5], rr[6],  rr[7]);
                    wA[2] = make_float4(rr[8], rr[9], rr[10], rr[11]);
                }
                if (i == K + 3) {
                    const int cp = (K + 3) >> 2;
                    float4* w4 = reinterpret_cast<float4*>(wbS + 64);
                    {   // colB: KEEP own diag (j == K+3); zero j < K+3
                        float4 v;
                        v.x = (4*cp+0 > K+2) ? a[4*cp+0] : 0.f;
                        v.y = (4*cp+1 > K+2) ? a[4*cp+1] : 0.f;
                        v.z = (4*cp+2 > K+2) ? a[4*cp+2] : 0.f;
                        v.w = (4*cp+3 > K+2) ? a[4*cp+3] : 0.f;
                        w4[cp] = v;
                    }
#pragma unroll
                    for (int c = cp + 1; c < 16; c++)
                        w4[c] = make_float4(a[4*c+0], a[4*c+1], a[4*c+2], a[4*c+3]);
                    float4* wB = reinterpret_cast<float4*>(wbS + 144);
                    wB[0] = make_float4(rr[0], rr[1], rr[2],  rr[3]);
                    wB[1] = make_float4(rr[4], rr[5], rr[6],  rr[7]);
                    wB[2] = make_float4(rr[8], rr[9], rr[10], rr[11]);
                }
            }
        }

        // ---- dump raw L rows; store z = forward-solve result
#pragma unroll
        for (int j = 0; j < NNB; j++) E->spdA[i][j] = a[j];
#pragma unroll
        for (int r = 0; r < RMAX; r++) E->u.p2.zs[i][r] = rr[r] * mydv;
        EBAR(barid);

        // ---- warp-local backward solve (zero barriers), RHS split across 2 warps
        {
            const int wsub  = (tid >> 5) & 1;
            const int lane  = tid & 31;
            const int RHs   = (R + 1) >> 1;
            const int rbase = wsub ? RHs : 0;
            const int rend  = wsub ? R   : RHs;

            float accL[6], accH[6], pred[6], sig[6], fk[6];
#pragma unroll
            for (int r = 0; r < 6; r++) { accL[r]=0.f; accH[r]=0.f; pred[r]=0.f; sig[r]=0.f; }

#pragma unroll
            for (int kk = 0; kk < NNB; kk++) {
                const int k = NNB - 1 - kk;
                const float dv = E->sdinv[k];
#pragma unroll
                for (int r = 0; r < 6; r++) {
                    int rq = rbase + r; if (rq >= RMAX) rq = 0;
                    float accv = (k >= 32) ? accH[r] : accL[r];
                    fk[r] = (E->u.p2.zs[k][rq] - dv * accv) * dv;
                }
#pragma unroll
                for (int r = 0; r < 6; r++)
                    fk[r] = __shfl_sync(0xffffffffu, fk[r], k & 31);

                float rowL = E->spdA[k][lane];
                if (lane < k) {
#pragma unroll
                    for (int r = 0; r < 6; r++) accL[r] += rowL * fk[r];
                }
                if (k > 32) {
                    float rowH = E->spdA[k][lane + 32];
                    if (lane + 32 < k) {
#pragma unroll
                        for (int r = 0; r < 6; r++) accH[r] += rowH * fk[r];
                    }
                }
                if (lane == 0) {
                    float kc = E->sKc[k];
#pragma unroll
                    for (int r = 0; r < 6; r++) {
                        int rq = rbase + r; if (rq >= RMAX) rq = 0;
                        pred[r] += kc * fk[r];
                        sig[r]  += E->u.p2.sYo[k][rq] * fk[r];
                    }
                }
            }

            if (lane == 0) {
#pragma unroll
                for (int r = 0; r < 6; r++) {
                    int rg = rbase + r;
                    if (rg < rend) {
                        if (rg < nm) {
                            int m = S->gmem[g][rg];
                            out[b * MM + m]              = pred[r];
                            g_sig_partial[m * BATCH + b] = sig[r];
                        } else {
                            float var = 1.0f - pred[r];
                            for (int q = 0; q < nm; q++)
                                out[BATCH * MM + b * MM + S->gmem[g][q]] = var;
                        }
                    }
                }
            }
        }
        EBAR(barid);
    }

    // ---- last-block sigma reduction (deterministic fixed-order sum)
    __threadfence();
    __syncthreads();
    if (tid == 0) S->ticket = atomicAdd(&g_done, 1u);
    __syncthreads();
    if (S->ticket == gridDim.x - 1) {
        __threadfence();
        const int lane = tid & 31, w = tid >> 5;
        for (int m = 0; m < MM; m++) {
            float s = 0.f;
            for (int t = tid; t < BATCH; t += 128)
                s += g_sig_partial[m * BATCH + t];
#pragma unroll
            for (int off = 16; off > 0; off >>= 1)
                s += __shfl_down_sync(0xffffffffu, s, off);
            if (lane == 0) S->sred[w] = s;
            __syncthreads();
            if (tid == 0) {
                float tot = S->sred[0] + S->sred[1] + S->sred[2] + S->sred[3];
                out[2 * BATCH * MM + m] = tot / (float)(BATCH * NNB);
            }
            __syncthreads();
        }
        if (tid == 0) g_done = 0;        // reset for next graph replay
    }
}

extern "C" void kernel_launch(void* const* d_in, const int* in_sizes, int n_in,
                              void* d_out, int out_size)
{
    const float* x    = (const float*)d_in[0];
    const float* ls   = (const float*)d_in[1];
    const float* eps  = (const float*)d_in[2];
    const int*   bidx = (const int*)d_in[3];
    const int*   nidx = (const int*)d_in[4];
    const float* Y    = (const float*)d_in[5];
    float* out = (float*)d_out;

    cudaFuncSetAttribute(muygps_main, cudaFuncAttributeMaxDynamicSharedMemorySize,
                         (int)sizeof(BlockSmem));
    muygps_main<<<BATCH / 2, 128, sizeof(BlockSmem)>>>(x, ls, eps, bidx, nidx, Y, out);
}

// round 9
// speedup vs baseline: 1.9354x; 1.1392x over previous
#include <cuda_runtime.h>

#define BATCH 2048
#define NNB   64
#define MM    10
#define FEAT  40
#define RMAX  (MM + 1)      // rhs columns (models + Kcross)
#define RPAD  12

__device__ float g_sig_partial[MM * BATCH];
__device__ unsigned int g_done = 0;

// per-element named barrier: 64 threads (2 warps), ids 1,2
#define EBAR(id) asm volatile("bar.sync %0, 64;" :: "r"(id) : "memory")

struct __align__(16) ElemSmem {
    float spdA[NNB][NNB + 1];            // dot-acc -> distances (never overwritten)
    union {
        struct {                          // phase 1 (feature tiles of 16/16/8)
            float sxn[NNB][16];
            float sxb[16];
            float snorm[NNB];
            int   sidx[NNB];
        } p1;
        struct {                          // phase 2
            float srow[2][176];           // [0..63] colA, [64..127] colB,
                                          // [128..139] rhsA, [144..155] rhsB, [160] dv2a
        } p2;
    } u;
    float red[2][2 * MM + 1];             // per-warp reduction scratch
};

struct BlockSmem {
    ElemSmem e[2];
    float gls[MM], geps[MM];
    int   gcnt[MM];
    int   gmem[MM][MM];
    int   ng;
    unsigned int ticket;
    float sred[4];
};

__global__ void __launch_bounds__(128, 5)
muygps_main(const float* __restrict__ x,
            const float* __restrict__ ls,
            const float* __restrict__ eps,
            const int*   __restrict__ bidx,
            const int*   __restrict__ nidx,
            const float* __restrict__ Y,
            float*       __restrict__ out)
{
    extern __shared__ char smem_raw[];
    BlockSmem* S = reinterpret_cast<BlockSmem*>(smem_raw);
    const int tid   = threadIdx.x;
    const int e     = tid >> 6;
    const int i     = tid & 63;
    const int barid = 1 + e;
    const int b     = blockIdx.x * 2 + e;
    ElemSmem* E = &S->e[e];

    if (tid == 0) {
        int ng = 0;
        for (int m = 0; m < MM; m++) {
            float lm = ls[m], em = eps[m];
            int g = -1;
            for (int q = 0; q < ng; q++)
                if (S->gls[q] == lm && S->geps[q] == em) { g = q; break; }
            if (g < 0) { g = ng++; S->gls[g] = lm; S->geps[g] = em; S->gcnt[g] = 0; }
            S->gmem[g][S->gcnt[g]++] = m;
        }
        S->ng = ng;
    }

    const int myidx = nidx[b * NNB + i];
    const float* xrow = x + (size_t)myidx * FEAT;
    const float* xb   = x + (size_t)bidx[b] * FEAT;

    // ---- phase 1: 3 feature tiles (16,16,8); dots accumulate in spdA
    float nrm = 0.f, cd2 = 0.f;
#pragma unroll
    for (int t = 0; t < 3; t++) {
        const int f0  = (t == 0) ? 0 : (t == 1) ? 16 : 32;
        const int len = (t < 2) ? 16 : 8;
        float xi[16];
        {
            const float4* xr = reinterpret_cast<const float4*>(xrow + f0);
            float4* sx = reinterpret_cast<float4*>(E->u.p1.sxn[i]);
#pragma unroll
            for (int q = 0; q < len / 4; q++) {
                float4 v = xr[q];
                sx[q] = v;
                xi[4*q+0]=v.x; xi[4*q+1]=v.y; xi[4*q+2]=v.z; xi[4*q+3]=v.w;
                nrm += v.x*v.x + v.y*v.y + v.z*v.z + v.w*v.w;
            }
        }
        if (i < len) E->u.p1.sxb[i] = xb[f0 + i];
        if (t == 0)  E->u.p1.sidx[i] = myidx;
        EBAR(barid);
#pragma unroll
        for (int f = 0; f < len; f++) { float d = xi[f] - E->u.p1.sxb[f]; cd2 += d * d; }
        for (int j = 0; j < NNB; j++) {
            const float4* vr = reinterpret_cast<const float4*>(E->u.p1.sxn[j]);
            float d0=0.f,d1=0.f,d2=0.f,d3=0.f;
#pragma unroll
            for (int q = 0; q < len / 4; q++) {
                float4 v = vr[q];
                d0 += xi[4*q+0]*v.x; d1 += xi[4*q+1]*v.y;
                d2 += xi[4*q+2]*v.z; d3 += xi[4*q+3]*v.w;
            }
            float dot = (d0+d1)+(d2+d3);
            if (t == 0) E->spdA[i][j] = dot;
            else        E->spdA[i][j] += dot;
        }
        EBAR(barid);
    }
    E->u.p1.snorm[i] = nrm;
    const float cdist = (cd2 > 0.f) ? sqrtf(cd2) : 0.f;   // crosswise (register, per thread)
    EBAR(barid);
    {
        const float ni = nrm;
        for (int j = 0; j < NNB; j++) {
            float dd = ni + E->u.p1.snorm[j] - 2.f * E->spdA[i][j];
            if (E->u.p1.sidx[j] == myidx) dd = 0.f;
            E->spdA[i][j] = (dd > 0.f) ? sqrtf(dd) : 0.f;
        }
    }
    __syncthreads();            // finalize done (p1 reads) + group table visible

    const float* Yrow = Y + ((size_t)b * NNB + i) * MM;
    const int ng = S->ng;

    for (int g = 0; g < ng; g++) {
        const float inv_ls = 1.0f / S->gls[g];
        const float epg    = S->geps[g];
        const int   nm     = S->gcnt[g];

        float* srowA = E->u.p2.srow[0];
        float* srowB = E->u.p2.srow[1];

        // ---- register row of Kp (spdA preserved across groups)
        float a[NNB];
#pragma unroll
        for (int j = 0; j < NNB; j++) {
            float v = __expf(-E->spdA[i][j] * inv_ls);
            a[j] = (j == i) ? v + epg : v;
        }
        const float Kc = __expf(-cdist * inv_ls);

        // ---- rhs registers
        float rr[RPAD];
#pragma unroll
        for (int r = 0; r < RPAD; r++) rr[r] = 0.f;
#pragma unroll
        for (int r = 0; r < MM; r++)
            if (r < nm) rr[r] = Yrow[S->gmem[g][r]];
#pragma unroll
        for (int r = 0; r < RMAX; r++)
            if (r == nm) rr[r] = Kc;

        float mydv = 0.f;

        // ---- bootstrap: row 0 (colA: diag zeroed, dv2 separate) and
        //      row 1 (colB: DIAG KEPT — consumers need it for diagB)
        if (i == 0) {
            float dv = rsqrtf(a[0]);
            mydv = dv;
            srowA[160] = dv * dv;
            float4* w4 = reinterpret_cast<float4*>(srowA);
            w4[0] = make_float4(0.f, a[1], a[2], a[3]);
#pragma unroll
            for (int c = 1; c < 16; c++)
                w4[c] = make_float4(a[4*c+0], a[4*c+1], a[4*c+2], a[4*c+3]);
            float4* wA = reinterpret_cast<float4*>(srowA + 128);
            wA[0] = make_float4(rr[0], rr[1], rr[2],  rr[3]);
            wA[1] = make_float4(rr[4], rr[5], rr[6],  rr[7]);
            wA[2] = make_float4(rr[8], rr[9], rr[10], rr[11]);
        }
        if (i == 1) {
            float4* w4 = reinterpret_cast<float4*>(srowA + 64);
            w4[0] = make_float4(0.f, a[1], a[2], a[3]);   // keep diag a[1]
#pragma unroll
            for (int c = 1; c < 16; c++)
                w4[c] = make_float4(a[4*c+0], a[4*c+1], a[4*c+2], a[4*c+3]);
            float4* wB = reinterpret_cast<float4*>(srowA + 144);
            wB[0] = make_float4(rr[0], rr[1], rr[2],  rr[3]);
            wB[1] = make_float4(rr[4], rr[5], rr[6],  rr[7]);
            wB[2] = make_float4(rr[8], rr[9], rr[10], rr[11]);
        }

        // ---- double-step Cholesky + fused forward solve: 32 barriers total
#pragma unroll
        for (int K = 0; K < NNB; K += 2) {
            EBAR(barid);
            const float* rbS = ((K >> 1) & 1) ? srowB : srowA;
            float*       wbS = ((K >> 1) & 1) ? srowA : srowB;

            const float dv2a  = rbS[160];
            const float cak1  = rbS[K + 1];
            const float cbk1  = rbS[64 + K + 1];     // row K+1 diagonal (kept)
            const float cc    = cak1 * dv2a;
            const float diagB = __fmaf_rn(-cc, cak1, cbk1);
            const float sdb   = rsqrtf(diagB);
            const float dv2b  = sdb * sdb;
            const float t1    = a[K] * dv2a;
            const float t2    = (a[K + 1] - t1 * cak1) * dv2b;

            if (i == K + 1) {
                mydv = sdb;
                const float4* rA4 = reinterpret_cast<const float4*>(rbS + 128);
#pragma unroll
                for (int c = 0; c < 3; c++) {
                    float4 va = rA4[c];
                    rr[4*c+0] -= t1 * va.x; rr[4*c+1] -= t1 * va.y;
                    rr[4*c+2] -= t1 * va.z; rr[4*c+3] -= t1 * va.w;
                }
            }
            if (K < NNB - 2 && i >= K + 2) {
                const float4* r4a = reinterpret_cast<const float4*>(rbS);
                const float4* r4b = reinterpret_cast<const float4*>(rbS + 64);
                const int c0 = (K + 2) >> 2;
                {   // boundary chunk: t2 term masked for j <= K+1 (compile-time)
                    float4 va = r4a[c0], vb = r4b[c0];
                    float b0 = (4*c0+0 > K+1) ? (vb.x - cc * va.x) : 0.f;
                    float b1 = (4*c0+1 > K+1) ? (vb.y - cc * va.y) : 0.f;
                    float b2 = (4*c0+2 > K+1) ? (vb.z - cc * va.z) : 0.f;
                    float b3 = (4*c0+3 > K+1) ? (vb.w - cc * va.w) : 0.f;
                    a[4*c0+0] -= t1 * va.x; a[4*c0+0] -= t2 * b0;
                    a[4*c0+1] -= t1 * va.y; a[4*c0+1] -= t2 * b1;
                    a[4*c0+2] -= t1 * va.z; a[4*c0+2] -= t2 * b2;
                    a[4*c0+3] -= t1 * va.w; a[4*c0+3] -= t2 * b3;
                }
#pragma unroll
                for (int c = c0 + 1; c < 16; c++) {
                    float4 va = r4a[c], vb = r4b[c];
                    a[4*c+0] -= t1 * va.x; a[4*c+0] -= t2 * (vb.x - cc * va.x);
                    a[4*c+1] -= t1 * va.y; a[4*c+1] -= t2 * (vb.y - cc * va.y);
                    a[4*c+2] -= t1 * va.z; a[4*c+2] -= t2 * (vb.z - cc * va.z);
                    a[4*c+3] -= t1 * va.w; a[4*c+3] -= t2 * (vb.w - cc * va.w);
                }
                const float4* rA4 = reinterpret_cast<const float4*>(rbS + 128);
                const float4* rB4 = reinterpret_cast<const float4*>(rbS + 144);
#pragma unroll
                for (int c = 0; c < 3; c++) {
                    float4 va = rA4[c], vb = rB4[c];
                    rr[4*c+0] -= t1 * va.x; rr[4*c+0] -= t2 * (vb.x - cc * va.x);
                    rr[4*c+1] -= t1 * va.y; rr[4*c+1] -= t2 * (vb.y - cc * va.y);
                    rr[4*c+2] -= t1 * va.z; rr[4*c+2] -= t2 * (vb.z - cc * va.z);
                    rr[4*c+3] -= t1 * va.w; rr[4*c+3] -= t2 * (vb.w - cc * va.w);
                }

                // publishes for next interval (pivot-style)
                if (i == K + 2) {
                    float dv = rsqrtf(a[K + 2]);
                    mydv = dv;
                    wbS[160] = dv * dv;
                    const int cp = (K + 2) >> 2;
                    float4* w4 = reinterpret_cast<float4*>(wbS);
                    {   // colA: zero j <= K+2 (diag via dv2), keep j >= K+3
                        float4 v;
                        v.x = (4*cp+0 > K+2) ? a[4*cp+0] : 0.f;
                        v.y = (4*cp+1 > K+2) ? a[4*cp+1] : 0.f;
                        v.z = (4*cp+2 > K+2) ? a[4*cp+2] : 0.f;
                        v.w = (4*cp+3 > K+2) ? a[4*cp+3] : 0.f;
                        w4[cp] = v;
                    }
#pragma unroll
                    for (int c = cp + 1; c < 16; c++)
                        w4[c] = make_float4(a[4*c+0], a[4*c+1], a[4*c+2], a[4*c+3]);
                    float4* wA = reinterpret_cast<float4*>(wbS + 128);
                    wA[0] = make_float4(rr[0], rr[1], rr[2],  rr[3]);
                    wA[1] = make_float4(rr[4], rr[5], rr[6],  rr[7]);
                    wA[2] = make_float4(rr[8], rr[9], rr[10], rr[11]);
                }
                if (i == K + 3) {
                    const int cp = (K + 3) >> 2;
                    float4* w4 = reinterpret_cast<float4*>(wbS + 64);
                    {   // colB: KEEP own diag (j == K+3); zero j < K+3
                        float4 v;
                        v.x = (4*cp+0 > K+2) ? a[4*cp+0] : 0.f;
                        v.y = (4*cp+1 > K+2) ? a[4*cp+1] : 0.f;
                        v.z = (4*cp+2 > K+2) ? a[4*cp+2] : 0.f;
                        v.w = (4*cp+3 > K+2) ? a[4*cp+3] : 0.f;
                        w4[cp] = v;
                    }
#pragma unroll
                    for (int c = cp + 1; c < 16; c++)
                        w4[c] = make_float4(a[4*c+0], a[4*c+1], a[4*c+2], a[4*c+3]);
                    float4* wB = reinterpret_cast<float4*>(wbS + 144);
                    wB[0] = make_float4(rr[0], rr[1], rr[2],  rr[3]);
                    wB[1] = make_float4(rr[4], rr[5], rr[6],  rr[7]);
                    wB[2] = make_float4(rr[8], rr[9], rr[10], rr[11]);
                }
            }
        }

        // ---- zs = D^{-1/2} L^{-1} rhs is now in rr (scaled by own dv).
        //      NO BACKWARD SOLVE: pred/var/sigma are inner products of zs columns.
#pragma unroll
        for (int r = 0; r < RPAD; r++) rr[r] *= mydv;

        float zKc = 0.f;
#pragma unroll
        for (int r = 0; r < RMAX; r++)
            if (r == nm) zKc = rr[r];

        float pm[MM], sg[MM];
#pragma unroll
        for (int r = 0; r < MM; r++) { pm[r] = rr[r] * zKc; sg[r] = rr[r] * rr[r]; }
        float vv = zKc * zKc;

#pragma unroll
        for (int off = 16; off > 0; off >>= 1) {
#pragma unroll
            for (int r = 0; r < MM; r++) {
                pm[r] += __shfl_xor_sync(0xffffffffu, pm[r], off);
                sg[r] += __shfl_xor_sync(0xffffffffu, sg[r], off);
            }
            vv += __shfl_xor_sync(0xffffffffu, vv, off);
        }
        {
            const int w = (tid >> 5) & 1, lane = tid & 31;
            if (lane == 0) {
#pragma unroll
                for (int r = 0; r < MM; r++) {
                    E->red[w][r]      = pm[r];
                    E->red[w][MM + r] = sg[r];
                }
                E->red[w][2 * MM] = vv;
            }
        }
        EBAR(barid);
        if (i == 0) {
            float var = 1.0f - (E->red[0][2*MM] + E->red[1][2*MM]);
            for (int r = 0; r < nm; r++) {
                int m = S->gmem[g][r];
                out[b * MM + m]              = E->red[0][r] + E->red[1][r];
                out[BATCH * MM + b * MM + m] = var;
                g_sig_partial[m * BATCH + b] = E->red[0][MM+r] + E->red[1][MM+r];
            }
        }
        EBAR(barid);     // protect red/srow before next group
    }

    // ---- last-block sigma reduction (deterministic fixed-order sum)
    __threadfence();
    __syncthreads();
    if (tid == 0) S->ticket = atomicAdd(&g_done, 1u);
    __syncthreads();
    if (S->ticket == gridDim.x - 1) {
        __threadfence();
        const int lane = tid & 31, w = tid >> 5;
        for (int m = 0; m < MM; m++) {
            float s = 0.f;
            for (int t = tid; t < BATCH; t += 128)
                s += g_sig_partial[m * BATCH + t];
#pragma unroll
            for (int off = 16; off > 0; off >>= 1)
                s += __shfl_down_sync(0xffffffffu, s, off);
            if (lane == 0) S->sred[w] = s;
            __syncthreads();
            if (tid == 0) {
                float tot = S->sred[0] + S->sred[1] + S->sred[2] + S->sred[3];
                out[2 * BATCH * MM + m] = tot / (float)(BATCH * NNB);
            }
            __syncthreads();
        }
        if (tid == 0) g_done = 0;        // reset for next graph replay
    }
}

extern "C" void kernel_launch(void* const* d_in, const int* in_sizes, int n_in,
                              void* d_out, int out_size)
{
    const float* x    = (const float*)d_in[0];
    const float* ls   = (const float*)d_in[1];
    const float* eps  = (const float*)d_in[2];
    const int*   bidx = (const int*)d_in[3];
    const int*   nidx = (const int*)d_in[4];
    const float* Y    = (const float*)d_in[5];
    float* out = (float*)d_out;

    cudaFuncSetAttribute(muygps_main, cudaFuncAttributeMaxDynamicSharedMemorySize,
                         (int)sizeof(BlockSmem));
    muygps_main<<<BATCH / 2, 128, sizeof(BlockSmem)>>>(x, ls, eps, bidx, nidx, Y, out);
}

// round 10
// speedup vs baseline: 2.2743x; 1.1751x over previous
#include <cuda_runtime.h>

#define BATCH 2048
#define NNB   64
#define MM    10
#define FEAT  40
#define RMAX  (MM + 1)
#define RPAD  12

typedef unsigned long long ull;

__device__ float g_sig_partial[MM * BATCH];
__device__ unsigned int g_done = 0;

#define EBAR(id) asm volatile("bar.sync %0, 64;" :: "r"(id) : "memory")

__device__ __forceinline__ ull pack2(float lo, float hi) {
    ull r; asm("mov.b64 %0, {%1, %2};" : "=l"(r) : "f"(lo), "f"(hi)); return r;
}
__device__ __forceinline__ void unpack2(ull v, float& lo, float& hi) {
    asm("mov.b64 {%0, %1}, %2;" : "=f"(lo), "=f"(hi) : "l"(v));
}
__device__ __forceinline__ ull fma2(ull a, ull b, ull c) {
    ull r; asm("fma.rn.f32x2 %0, %1, %2, %3;" : "=l"(r) : "l"(a), "l"(b), "l"(c)); return r;
}
__device__ __forceinline__ ull mul2(ull a, ull b) {
    ull r; asm("mul.rn.f32x2 %0, %1, %2;" : "=l"(r) : "l"(a), "l"(b)); return r;
}
__device__ __forceinline__ ull zero_lo(ull v) {   // (0, hi)
    float lo, hi; unpack2(v, lo, hi); return pack2(0.f, hi);
}

struct __align__(16) ElemSmem {
    float spdA[NNB][NNB + 1];            // dot-acc -> distances (never overwritten)
    union {
        struct {                          // phase 1 (feature tiles 16/16/8)
            float sxn[NNB][16];
            float sxb[16];
            float snorm[NNB];
            int   sidx[NNB];
        } p1;
        struct {                          // phase 2
            float srow[2][176];           // [0..63] colA, [64..127] colB,
                                          // [128..139] rhsA, [144..155] rhsB, [160] dv2a
        } p2;
    } u;
    float red[2][2 * MM + 1];
};

struct BlockSmem {
    ElemSmem e[2];
    float gls[MM], geps[MM];
    int   gcnt[MM];
    int   gmem[MM][MM];
    int   ng;
    unsigned int ticket;
    float sred[4];
};

__global__ void __launch_bounds__(128, 5)
muygps_main(const float* __restrict__ x,
            const float* __restrict__ ls,
            const float* __restrict__ eps,
            const int*   __restrict__ bidx,
            const int*   __restrict__ nidx,
            const float* __restrict__ Y,
            float*       __restrict__ out)
{
    extern __shared__ char smem_raw[];
    BlockSmem* S = reinterpret_cast<BlockSmem*>(smem_raw);
    const int tid   = threadIdx.x;
    const int e     = tid >> 6;
    const int i     = tid & 63;
    const int barid = 1 + e;
    const int b     = blockIdx.x * 2 + e;
    ElemSmem* E = &S->e[e];

    if (tid == 0) {
        int ng = 0;
        for (int m = 0; m < MM; m++) {
            float lm = ls[m], em = eps[m];
            int g = -1;
            for (int q = 0; q < ng; q++)
                if (S->gls[q] == lm && S->geps[q] == em) { g = q; break; }
            if (g < 0) { g = ng++; S->gls[g] = lm; S->geps[g] = em; S->gcnt[g] = 0; }
            S->gmem[g][S->gcnt[g]++] = m;
        }
        S->ng = ng;
    }

    const int myidx = nidx[b * NNB + i];
    const float* xrow = x + (size_t)myidx * FEAT;
    const float* xb   = x + (size_t)bidx[b] * FEAT;

    // ---- phase 1: 3 feature tiles (16,16,8); packed dots accumulate in spdA
    ull  nrm2 = 0ull;
    float cd2 = 0.f;
#pragma unroll
    for (int t = 0; t < 3; t++) {
        const int f0  = (t == 0) ? 0 : (t == 1) ? 16 : 32;
        const int len = (t < 2) ? 16 : 8;
        ull xi2[8];
        {
            const ulonglong2* xr = reinterpret_cast<const ulonglong2*>(xrow + f0);
            ulonglong2* sx = reinterpret_cast<ulonglong2*>(E->u.p1.sxn[i]);
#pragma unroll
            for (int q = 0; q < len / 4; q++) {
                ulonglong2 v = xr[q];
                sx[q] = v;
                xi2[2*q] = v.x; xi2[2*q+1] = v.y;
                nrm2 = fma2(v.x, v.x, nrm2);
                nrm2 = fma2(v.y, v.y, nrm2);
            }
        }
        if (i < len) E->u.p1.sxb[i] = xb[f0 + i];
        if (t == 0)  E->u.p1.sidx[i] = myidx;
        EBAR(barid);
#pragma unroll
        for (int p = 0; p < len / 2; p++) {
            float l, h; unpack2(xi2[p], l, h);
            float d = l - E->u.p1.sxb[2*p];     cd2 += d * d;
            float d2 = h - E->u.p1.sxb[2*p+1];  cd2 += d2 * d2;
        }
        for (int j = 0; j < NNB; j++) {
            const ulonglong2* vr = reinterpret_cast<const ulonglong2*>(E->u.p1.sxn[j]);
            ull accA = 0ull, accB = 0ull;
#pragma unroll
            for (int q = 0; q < len / 4; q++) {
                ulonglong2 v = vr[q];
                accA = fma2(xi2[2*q],   v.x, accA);
                accB = fma2(xi2[2*q+1], v.y, accB);
            }
            float la, ha, lb, hb;
            unpack2(accA, la, ha); unpack2(accB, lb, hb);
            float dot = (la + lb) + (ha + hb);
            if (t == 0) E->spdA[i][j] = dot;
            else        E->spdA[i][j] += dot;
        }
        EBAR(barid);
    }
    {
        float nl, nh; unpack2(nrm2, nl, nh);
        E->u.p1.snorm[i] = nl + nh;
    }
    const float cdist = (cd2 > 0.f) ? sqrtf(cd2) : 0.f;
    EBAR(barid);
    {
        const float ni = E->u.p1.snorm[i];
        for (int j = 0; j < NNB; j++) {
            float dd = ni + E->u.p1.snorm[j] - 2.f * E->spdA[i][j];
            if (E->u.p1.sidx[j] == myidx) dd = 0.f;
            E->spdA[i][j] = (dd > 0.f) ? sqrtf(dd) : 0.f;
        }
    }
    __syncthreads();            // finalize + group table visible

    const float* Yrow = Y + ((size_t)b * NNB + i) * MM;
    const int ng = S->ng;

    for (int g = 0; g < ng; g++) {
        const float inv_ls = 1.0f / S->gls[g];
        const float epg    = S->geps[g];
        const int   nm     = S->gcnt[g];

        float* srowA = E->u.p2.srow[0];
        float* srowB = E->u.p2.srow[1];

        // ---- packed register row of Kp
        ull a2[NNB / 2];
#pragma unroll
        for (int p = 0; p < NNB / 2; p++) {
            float e0 = __expf(-E->spdA[i][2*p]   * inv_ls);
            float e1 = __expf(-E->spdA[i][2*p+1] * inv_ls);
            if (2*p   == i) e0 += epg;
            if (2*p+1 == i) e1 += epg;
            a2[p] = pack2(e0, e1);
        }
        const float Kc = __expf(-cdist * inv_ls);

        // ---- packed rhs
        ull rr2[6];
        {
            float rv[RPAD];
#pragma unroll
            for (int r = 0; r < RPAD; r++) rv[r] = 0.f;
#pragma unroll
            for (int r = 0; r < MM; r++)
                if (r < nm) rv[r] = Yrow[S->gmem[g][r]];
#pragma unroll
            for (int r = 0; r < RMAX; r++)
                if (r == nm) rv[r] = Kc;
#pragma unroll
            for (int p = 0; p < 6; p++) rr2[p] = pack2(rv[2*p], rv[2*p+1]);
        }

        float mydv = 0.f;

        // ---- bootstrap publishes: colA by row 0, colB by row 1 (diag kept)
        if (i == 0) {
            float a0, a1u; unpack2(a2[0], a0, a1u);
            float dv = rsqrtf(a0);
            mydv = dv;
            srowA[160] = dv * dv;
            ulonglong2* w = reinterpret_cast<ulonglong2*>(srowA);
#pragma unroll
            for (int c = 0; c < 16; c++) {
                ull p0 = (c == 0) ? zero_lo(a2[0]) : a2[2*c];
                w[c] = make_ulonglong2(p0, a2[2*c+1]);
            }
            ulonglong2* wA = reinterpret_cast<ulonglong2*>(srowA + 128);
            wA[0] = make_ulonglong2(rr2[0], rr2[1]);
            wA[1] = make_ulonglong2(rr2[2], rr2[3]);
            wA[2] = make_ulonglong2(rr2[4], rr2[5]);
        }
        if (i == 1) {
            ulonglong2* w = reinterpret_cast<ulonglong2*>(srowA + 64);
#pragma unroll
            for (int c = 0; c < 16; c++) {
                ull p0 = (c == 0) ? zero_lo(a2[0]) : a2[2*c];
                w[c] = make_ulonglong2(p0, a2[2*c+1]);
            }
            ulonglong2* wB = reinterpret_cast<ulonglong2*>(srowA + 144);
            wB[0] = make_ulonglong2(rr2[0], rr2[1]);
            wB[1] = make_ulonglong2(rr2[2], rr2[3]);
            wB[2] = make_ulonglong2(rr2[4], rr2[5]);
        }

        // ---- double-step Cholesky + fused forward solve (packed), 32 barriers
#pragma unroll
        for (int K = 0; K < NNB; K += 2) {
            EBAR(barid);
            const float* rbS = ((K >> 1) & 1) ? srowB : srowA;
            float*       wbS = ((K >> 1) & 1) ? srowA : srowB;

            const float dv2a  = rbS[160];
            const float cak1  = rbS[K + 1];
            const float cbk1  = rbS[64 + K + 1];
            const float cc    = cak1 * dv2a;
            const float diagB = __fmaf_rn(-cc, cak1, cbk1);
            const float sdb   = rsqrtf(diagB);
            const float dv2b  = sdb * sdb;
            float aKlo, aKhi; unpack2(a2[K / 2], aKlo, aKhi);
            const float t1 = aKlo * dv2a;
            const float t2 = __fmaf_rn(-t1, cak1, aKhi) * dv2b;
            const ull ncc2 = pack2(-cc, -cc);
            const ull nt12 = pack2(-t1, -t1);
            const ull nt22 = pack2(-t2, -t2);

            if (i == K + 1) {
                mydv = sdb;
                const ulonglong2* rA = reinterpret_cast<const ulonglong2*>(rbS + 128);
#pragma unroll
                for (int c = 0; c < 3; c++) {
                    ulonglong2 v = rA[c];
                    rr2[2*c]   = fma2(nt12, v.x, rr2[2*c]);
                    rr2[2*c+1] = fma2(nt12, v.y, rr2[2*c+1]);
                }
            }
            if (K < NNB - 2 && i >= K + 2) {
                const int c0  = (K + 2) >> 2;           // first float4 chunk
                const int pT1 = (K % 4 == 0) ? K / 2 : -1;   // t1-only pack
                const ulonglong2* r4a = reinterpret_cast<const ulonglong2*>(rbS);
                const ulonglong2* r4b = reinterpret_cast<const ulonglong2*>(rbS + 64);
#pragma unroll
                for (int c = c0; c < 16; c++) {
                    ulonglong2 va = r4a[c];
                    ulonglong2 vb = r4b[c];
                    if (2*c == pT1) {
                        a2[2*c] = fma2(nt12, va.x, a2[2*c]);
                    } else {
                        ull bb = fma2(ncc2, va.x, vb.x);
                        a2[2*c] = fma2(nt12, va.x, a2[2*c]);
                        a2[2*c] = fma2(nt22, bb,   a2[2*c]);
                    }
                    {
                        ull bb = fma2(ncc2, va.y, vb.y);
                        a2[2*c+1] = fma2(nt12, va.y, a2[2*c+1]);
                        a2[2*c+1] = fma2(nt22, bb,   a2[2*c+1]);
                    }
                }
                {
                    const ulonglong2* rA = reinterpret_cast<const ulonglong2*>(rbS + 128);
                    const ulonglong2* rB = reinterpret_cast<const ulonglong2*>(rbS + 144);
#pragma unroll
                    for (int c = 0; c < 3; c++) {
                        ulonglong2 vA = rA[c], vB = rB[c];
                        ull b0 = fma2(ncc2, vA.x, vB.x);
                        ull b1 = fma2(ncc2, vA.y, vB.y);
                        rr2[2*c]   = fma2(nt12, vA.x, rr2[2*c]);
                        rr2[2*c]   = fma2(nt22, b0,   rr2[2*c]);
                        rr2[2*c+1] = fma2(nt12, vA.y, rr2[2*c+1]);
                        rr2[2*c+1] = fma2(nt22, b1,   rr2[2*c+1]);
                    }
                }

                // publishes for next interval K' = K+2
                const int cp  = (K + 2) >> 2;           // first chunk to store
                const int cp2 = (K + 2) / 2;            // pack holding (K+2, K+3)
                if (i == K + 2) {
                    float dlo, dhi; unpack2(a2[cp2], dlo, dhi);
                    float dv = rsqrtf(dlo);
                    mydv = dv;
                    wbS[160] = dv * dv;
                    ulonglong2* w = reinterpret_cast<ulonglong2*>(wbS);
#pragma unroll
                    for (int c = cp; c < 16; c++) {
                        ull p0 = (2*c < cp2) ? 0ull : (2*c == cp2) ? zero_lo(a2[2*c]) : a2[2*c];
                        ull p1 = (2*c+1 == cp2) ? zero_lo(a2[2*c+1]) : a2[2*c+1];
                        w[c] = make_ulonglong2(p0, p1);
                    }
                    ulonglong2* wA = reinterpret_cast<ulonglong2*>(wbS + 128);
                    wA[0] = make_ulonglong2(rr2[0], rr2[1]);
                    wA[1] = make_ulonglong2(rr2[2], rr2[3]);
                    wA[2] = make_ulonglong2(rr2[4], rr2[5]);
                }
                if (i == K + 3) {
                    ulonglong2* w = reinterpret_cast<ulonglong2*>(wbS + 64);
#pragma unroll
                    for (int c = cp; c < 16; c++) {
                        ull p0 = (2*c < cp2) ? 0ull : (2*c == cp2) ? zero_lo(a2[2*c]) : a2[2*c];
                        ull p1 = (2*c+1 == cp2) ? zero_lo(a2[2*c+1]) : a2[2*c+1];
                        w[c] = make_ulonglong2(p0, p1);
                    }
                    ulonglong2* wB = reinterpret_cast<ulonglong2*>(wbS + 144);
                    wB[0] = make_ulonglong2(rr2[0], rr2[1]);
                    wB[1] = make_ulonglong2(rr2[2], rr2[3]);
                    wB[2] = make_ulonglong2(rr2[4], rr2[5]);
                }
            }
        }

        // ---- zs in rr2 (scale by own dv); outputs are inner products
        {
            ull mv2 = pack2(mydv, mydv);
#pragma unroll
            for (int p = 0; p < 6; p++) rr2[p] = mul2(rr2[p], mv2);
        }
        float z[RPAD];
#pragma unroll
        for (int p = 0; p < 6; p++) unpack2(rr2[p], z[2*p], z[2*p+1]);

        float zKc = 0.f;
#pragma unroll
        for (int r = 0; r < RMAX; r++)
            if (r == nm) zKc = z[r];

        float pm[MM], sg[MM];
#pragma unroll
        for (int r = 0; r < MM; r++) { pm[r] = z[r] * zKc; sg[r] = z[r] * z[r]; }
        float vv = zKc * zKc;

#pragma unroll
        for (int off = 16; off > 0; off >>= 1) {
#pragma unroll
            for (int r = 0; r < MM; r++) {
                pm[r] += __shfl_xor_sync(0xffffffffu, pm[r], off);
                sg[r] += __shfl_xor_sync(0xffffffffu, sg[r], off);
            }
            vv += __shfl_xor_sync(0xffffffffu, vv, off);
        }
        {
            const int w = (tid >> 5) & 1, lane = tid & 31;
            if (lane == 0) {
#pragma unroll
                for (int r = 0; r < MM; r++) {
                    E->red[w][r]      = pm[r];
                    E->red[w][MM + r] = sg[r];
                }
                E->red[w][2 * MM] = vv;
            }
        }
        EBAR(barid);
        if (i == 0) {
            float var = 1.0f - (E->red[0][2*MM] + E->red[1][2*MM]);
            for (int r = 0; r < nm; r++) {
                int m = S->gmem[g][r];
                out[b * MM + m]              = E->red[0][r] + E->red[1][r];
                out[BATCH * MM + b * MM + m] = var;
                g_sig_partial[m * BATCH + b] = E->red[0][MM+r] + E->red[1][MM+r];
            }
        }
        EBAR(barid);
    }

    // ---- last-block sigma reduction (deterministic fixed-order sum)
    __threadfence();
    __syncthreads();
    if (tid == 0) S->ticket = atomicAdd(&g_done, 1u);
    __syncthreads();
    if (S->ticket == gridDim.x - 1) {
        __threadfence();
        const int lane = tid & 31, w = tid >> 5;
        for (int m = 0; m < MM; m++) {
            float s = 0.f;
            for (int t = tid; t < BATCH; t += 128)
                s += g_sig_partial[m * BATCH + t];
#pragma unroll
            for (int off = 16; off > 0; off >>= 1)
                s += __shfl_down_sync(0xffffffffu, s, off);
            if (lane == 0) S->sred[w] = s;
            __syncthreads();
            if (tid == 0) {
                float tot = S->sred[0] + S->sred[1] + S->sred[2] + S->sred[3];
                out[2 * BATCH * MM + m] = tot / (float)(BATCH * NNB);
            }
            __syncthreads();
        }
        if (tid == 0) g_done = 0;
    }
}

extern "C" void kernel_launch(void* const* d_in, const int* in_sizes, int n_in,
                              void* d_out, int out_size)
{
    const float* x    = (const float*)d_in[0];
    const float* ls   = (const float*)d_in[1];
    const float* eps  = (const float*)d_in[2];
    const int*   bidx = (const int*)d_in[3];
    const int*   nidx = (const int*)d_in[4];
    const float* Y    = (const float*)d_in[5];
    float* out = (float*)d_out;

    cudaFuncSetAttribute(muygps_main, cudaFuncAttributeMaxDynamicSharedMemorySize,
                         (int)sizeof(BlockSmem));
    muygps_main<<<BATCH / 2, 128, sizeof(BlockSmem)>>>(x, ls, eps, bidx, nidx, Y, out);
}

// round 11
// speedup vs baseline: 2.4711x; 1.0865x over previous
#include <cuda_runtime.h>

#define BATCH 2048
#define NNB   64
#define MM    10
#define FEAT  40
#define RMAX  (MM + 1)
#define RPAD  12
#define PDS   66            // spdA row stride: even (8B-packed) + 2-way-max banks

typedef unsigned long long ull;

__device__ float g_sig_partial[MM * BATCH];
__device__ unsigned int g_done = 0;

#define EBAR(id) asm volatile("bar.sync %0, 64;" :: "r"(id) : "memory")

__device__ __forceinline__ ull pack2(float lo, float hi) {
    ull r; asm("mov.b64 %0, {%1, %2};" : "=l"(r) : "f"(lo), "f"(hi)); return r;
}
__device__ __forceinline__ void unpack2(ull v, float& lo, float& hi) {
    asm("mov.b64 {%0, %1}, %2;" : "=f"(lo), "=f"(hi) : "l"(v));
}
__device__ __forceinline__ ull fma2(ull a, ull b, ull c) {
    ull r; asm("fma.rn.f32x2 %0, %1, %2, %3;" : "=l"(r) : "l"(a), "l"(b), "l"(c)); return r;
}
__device__ __forceinline__ ull add2(ull a, ull b) {
    ull r; asm("add.rn.f32x2 %0, %1, %2;" : "=l"(r) : "l"(a), "l"(b)); return r;
}
__device__ __forceinline__ ull mul2(ull a, ull b) {
    ull r; asm("mul.rn.f32x2 %0, %1, %2;" : "=l"(r) : "l"(a), "l"(b)); return r;
}
__device__ __forceinline__ ull zero_lo(ull v) {
    float lo, hi; unpack2(v, lo, hi); return pack2(0.f, hi);
}

struct __align__(16) ElemSmem {
    float spdA[NNB][PDS];                // raw pairwise DOTS (never finalized in smem)
    union {
        struct {                          // phase 1: transposed feature staging
            float sxnT[16][NNB];          // [feature][neighbor]
            float sxb[16];
        } p1;
        struct {                          // phase 2
            float srow[2][176];           // [0..63] colA, [64..127] colB,
                                          // [128..139] rhsA, [144..155] rhsB, [160] dv2a
        } p2;
    } u;
    float snorm[NNB];                     // outside union: read in phase 2
    int   sidx[NNB];
    float red[2][2 * MM + 1];
};

struct BlockSmem {
    ElemSmem e[2];
    float gls[MM], geps[MM];
    int   gcnt[MM];
    int   gmem[MM][MM];
    int   ng;
    unsigned int ticket;
    float sred[4];
};

__global__ void __launch_bounds__(128, 5)
muygps_main(const float* __restrict__ x,
            const float* __restrict__ ls,
            const float* __restrict__ eps,
            const int*   __restrict__ bidx,
            const int*   __restrict__ nidx,
            const float* __restrict__ Y,
            float*       __restrict__ out)
{
    extern __shared__ char smem_raw[];
    BlockSmem* S = reinterpret_cast<BlockSmem*>(smem_raw);
    const int tid   = threadIdx.x;
    const int e     = tid >> 6;
    const int i     = tid & 63;
    const int barid = 1 + e;
    const int b     = blockIdx.x * 2 + e;
    ElemSmem* E = &S->e[e];

    if (tid == 0) {
        int ng = 0;
        for (int m = 0; m < MM; m++) {
            float lm = ls[m], em = eps[m];
            int g = -1;
            for (int q = 0; q < ng; q++)
                if (S->gls[q] == lm && S->geps[q] == em) { g = q; break; }
            if (g < 0) { g = ng++; S->gls[g] = lm; S->geps[g] = em; S->gcnt[g] = 0; }
            S->gmem[g][S->gcnt[g]++] = m;
        }
        S->ng = ng;
    }

    const int myidx = nidx[b * NNB + i];
    const float* xrow = x + (size_t)myidx * FEAT;
    const float* xb   = x + (size_t)bidx[b] * FEAT;

    // ---- phase 1: 3 feature tiles (16,16,8); j-packed dots accumulate in spdA
    float nrm = 0.f, cd2 = 0.f;
#pragma unroll
    for (int t = 0; t < 3; t++) {
        const int f0  = (t == 0) ? 0 : (t == 1) ? 16 : 32;
        const int len = (t < 2) ? 16 : 8;
        ull xd[16];                         // per-feature duplicated packs
        {
            const ulonglong2* xr = reinterpret_cast<const ulonglong2*>(xrow + f0);
#pragma unroll
            for (int q = 0; q < len / 4; q++) {
                ulonglong2 v = xr[q];
                float f0v, f1v, f2v, f3v;
                unpack2(v.x, f0v, f1v);
                unpack2(v.y, f2v, f3v);
                xd[4*q+0] = pack2(f0v, f0v);
                xd[4*q+1] = pack2(f1v, f1v);
                xd[4*q+2] = pack2(f2v, f2v);
                xd[4*q+3] = pack2(f3v, f3v);
                E->u.p1.sxnT[4*q+0][i] = f0v;
                E->u.p1.sxnT[4*q+1][i] = f1v;
                E->u.p1.sxnT[4*q+2][i] = f2v;
                E->u.p1.sxnT[4*q+3][i] = f3v;
                nrm += f0v*f0v + f1v*f1v;
                nrm += f2v*f2v + f3v*f3v;
            }
        }
        if (i < len) E->u.p1.sxb[i] = xb[f0 + i];
        if (t == 0)  E->sidx[i] = myidx;
        EBAR(barid);

        // crosswise accumulation (scalar; xd lanes are duplicated feature values)
#pragma unroll
        for (int f = 0; f < len; f++) {
            float lo, hi; unpack2(xd[f], lo, hi);
            float d = lo - E->u.p1.sxb[f];
            cd2 += d * d;
        }

        // j-packed Gram: each LDS.128 broadcast = features of 4 neighbors
        {
            const ulonglong2* colb = reinterpret_cast<const ulonglong2*>(&E->u.p1.sxnT[0][0]);
#pragma unroll 4
            for (int g4 = 0; g4 < 16; g4++) {
                ull acc0 = 0ull, acc1 = 0ull;    // dots for (4g,4g+1) and (4g+2,4g+3)
#pragma unroll
                for (int f = 0; f < len; f++) {
                    ulonglong2 v = colb[16 * f + g4];
                    acc0 = fma2(xd[f], v.x, acc0);
                    acc1 = fma2(xd[f], v.y, acc1);
                }
                ull* dst = reinterpret_cast<ull*>(&E->spdA[i][4 * g4]);
                if (t == 0) {
                    dst[0] = acc0;
                    dst[1] = acc1;
                } else {
                    dst[0] = add2(dst[0], acc0);
                    dst[1] = add2(dst[1], acc1);
                }
            }
        }
        EBAR(barid);       // protect sxnT before next tile overwrites it
    }
    E->snorm[i] = nrm;
    const float cdist = (cd2 > 0.f) ? sqrtf(cd2) : 0.f;
    __syncthreads();       // snorm/sidx visible + group table visible

    const float* Yrow = Y + ((size_t)b * NNB + i) * MM;
    const int ng = S->ng;

    for (int g = 0; g < ng; g++) {
        const float inv_ls = 1.0f / S->gls[g];
        const float epg    = S->geps[g];
        const int   nm     = S->gcnt[g];

        float* srowA = E->u.p2.srow[0];
        float* srowB = E->u.p2.srow[1];

        // ---- packed Kp row built straight from raw dots (no finalize pass):
        //      d = sqrt(ni + nj - 2 dot), dup-masked; exactly symmetric
        ull a2[NNB / 2];
        {
            const float ni = nrm;
#pragma unroll
            for (int p = 0; p < NNB / 2; p++) {
                ull dot2 = *reinterpret_cast<const ull*>(&E->spdA[i][2 * p]);
                float d0, d1; unpack2(dot2, d0, d1);
                float n0 = E->snorm[2*p], n1 = E->snorm[2*p+1];
                float dd0 = ni + n0 - 2.f * d0;
                float dd1 = ni + n1 - 2.f * d1;
                if (E->sidx[2*p]   == myidx) dd0 = 0.f;
                if (E->sidx[2*p+1] == myidx) dd1 = 0.f;
                dd0 = (dd0 > 0.f) ? sqrtf(dd0) : 0.f;
                dd1 = (dd1 > 0.f) ? sqrtf(dd1) : 0.f;
                float e0 = __expf(-dd0 * inv_ls);
                float e1 = __expf(-dd1 * inv_ls);
                if (2*p   == i) e0 += epg;
                if (2*p+1 == i) e1 += epg;
                a2[p] = pack2(e0, e1);
            }
        }
        const float Kc = __expf(-cdist * inv_ls);

        // ---- packed rhs
        ull rr2[6];
        {
            float rv[RPAD];
#pragma unroll
            for (int r = 0; r < RPAD; r++) rv[r] = 0.f;
#pragma unroll
            for (int r = 0; r < MM; r++)
                if (r < nm) rv[r] = Yrow[S->gmem[g][r]];
#pragma unroll
            for (int r = 0; r < RMAX; r++)
                if (r == nm) rv[r] = Kc;
#pragma unroll
            for (int p = 0; p < 6; p++) rr2[p] = pack2(rv[2*p], rv[2*p+1]);
        }

        float mydv = 0.f;

        // ---- bootstrap publishes: colA by row 0, colB by row 1 (diag kept)
        if (i == 0) {
            float a0, a1u; unpack2(a2[0], a0, a1u);
            float dv = rsqrtf(a0);
            mydv = dv;
            srowA[160] = dv * dv;
            ulonglong2* w = reinterpret_cast<ulonglong2*>(srowA);
#pragma unroll
            for (int c = 0; c < 16; c++) {
                ull p0 = (c == 0) ? zero_lo(a2[0]) : a2[2*c];
                w[c] = make_ulonglong2(p0, a2[2*c+1]);
            }
            ulonglong2* wA = reinterpret_cast<ulonglong2*>(srowA + 128);
            wA[0] = make_ulonglong2(rr2[0], rr2[1]);
            wA[1] = make_ulonglong2(rr2[2], rr2[3]);
            wA[2] = make_ulonglong2(rr2[4], rr2[5]);
        }
        if (i == 1) {
            ulonglong2* w = reinterpret_cast<ulonglong2*>(srowA + 64);
#pragma unroll
            for (int c = 0; c < 16; c++) {
                ull p0 = (c == 0) ? zero_lo(a2[0]) : a2[2*c];
                w[c] = make_ulonglong2(p0, a2[2*c+1]);
            }
            ulonglong2* wB = reinterpret_cast<ulonglong2*>(srowA + 144);
            wB[0] = make_ulonglong2(rr2[0], rr2[1]);
            wB[1] = make_ulonglong2(rr2[2], rr2[3]);
            wB[2] = make_ulonglong2(rr2[4], rr2[5]);
        }

        // ---- double-step Cholesky + fused forward solve (packed), 32 barriers
#pragma unroll
        for (int K = 0; K < NNB; K += 2) {
            EBAR(barid);
            const float* rbS = ((K >> 1) & 1) ? srowB : srowA;
            float*       wbS = ((K >> 1) & 1) ? srowA : srowB;

            const float dv2a  = rbS[160];
            const float cak1  = rbS[K + 1];
            const float cbk1  = rbS[64 + K + 1];
            const float cc    = cak1 * dv2a;
            const float diagB = __fmaf_rn(-cc, cak1, cbk1);
            const float sdb   = rsqrtf(diagB);
            const float dv2b  = sdb * sdb;
            float aKlo, aKhi; unpack2(a2[K / 2], aKlo, aKhi);
            const float t1 = aKlo * dv2a;
            const float t2 = __fmaf_rn(-t1, cak1, aKhi) * dv2b;
            const ull ncc2 = pack2(-cc, -cc);
            const ull nt12 = pack2(-t1, -t1);
            const ull nt22 = pack2(-t2, -t2);

            if (i == K + 1) {
                mydv = sdb;
                const ulonglong2* rA = reinterpret_cast<const ulonglong2*>(rbS + 128);
#pragma unroll
                for (int c = 0; c < 3; c++) {
                    ulonglong2 v = rA[c];
                    rr2[2*c]   = fma2(nt12, v.x, rr2[2*c]);
                    rr2[2*c+1] = fma2(nt12, v.y, rr2[2*c+1]);
                }
            }
            if (K < NNB - 2 && i >= K + 2) {
                const int c0  = (K + 2) >> 2;
                const int pT1 = (K % 4 == 0) ? K / 2 : -1;   // t1-only pack
                const ulonglong2* r4a = reinterpret_cast<const ulonglong2*>(rbS);
                const ulonglong2* r4b = reinterpret_cast<const ulonglong2*>(rbS + 64);
#pragma unroll
                for (int c = c0; c < 16; c++) {
                    ulonglong2 va = r4a[c];
                    ulonglong2 vb = r4b[c];
                    if (2*c == pT1) {
                        a2[2*c] = fma2(nt12, va.x, a2[2*c]);
                    } else {
                        ull bb = fma2(ncc2, va.x, vb.x);
                        a2[2*c] = fma2(nt12, va.x, a2[2*c]);
                        a2[2*c] = fma2(nt22, bb,   a2[2*c]);
                    }
                    {
                        ull bb = fma2(ncc2, va.y, vb.y);
                        a2[2*c+1] = fma2(nt12, va.y, a2[2*c+1]);
                        a2[2*c+1] = fma2(nt22, bb,   a2[2*c+1]);
                    }
                }
                {
                    const ulonglong2* rA = reinterpret_cast<const ulonglong2*>(rbS + 128);
                    const ulonglong2* rB = reinterpret_cast<const ulonglong2*>(rbS + 144);
#pragma unroll
                    for (int c = 0; c < 3; c++) {
                        ulonglong2 vA = rA[c], vB = rB[c];
                        ull b0 = fma2(ncc2, vA.x, vB.x);
                        ull b1 = fma2(ncc2, vA.y, vB.y);
                        rr2[2*c]   = fma2(nt12, vA.x, rr2[2*c]);
                        rr2[2*c]   = fma2(nt22, b0,   rr2[2*c]);
                        rr2[2*c+1] = fma2(nt12, vA.y, rr2[2*c+1]);
                        rr2[2*c+1] = fma2(nt22, b1,   rr2[2*c+1]);
                    }
                }

                // publishes for next interval K' = K+2
                const int cp  = (K + 2) >> 2;
                const int cp2 = (K + 2) / 2;
                if (i == K + 2) {
                    float dlo, dhi; unpack2(a2[cp2], dlo, dhi);
                    float dv = rsqrtf(dlo);
                    mydv = dv;
                    wbS[160] = dv * dv;
                    ulonglong2* w = reinterpret_cast<ulonglong2*>(wbS);
#pragma unroll
                    for (int c = cp; c < 16; c++) {
                        ull p0 = (2*c < cp2) ? 0ull : (2*c == cp2) ? zero_lo(a2[2*c]) : a2[2*c];
                        ull p1 = (2*c+1 == cp2) ? zero_lo(a2[2*c+1]) : a2[2*c+1];
                        w[c] = make_ulonglong2(p0, p1);
                    }
                    ulonglong2* wA = reinterpret_cast<ulonglong2*>(wbS + 128);
                    wA[0] = make_ulonglong2(rr2[0], rr2[1]);
                    wA[1] = make_ulonglong2(rr2[2], rr2[3]);
                    wA[2] = make_ulonglong2(rr2[4], rr2[5]);
                }
                if (i == K + 3) {
                    ulonglong2* w = reinterpret_cast<ulonglong2*>(wbS + 64);
#pragma unroll
                    for (int c = cp; c < 16; c++) {
                        ull p0 = (2*c < cp2) ? 0ull : (2*c == cp2) ? zero_lo(a2[2*c]) : a2[2*c];
                        ull p1 = (2*c+1 == cp2) ? zero_lo(a2[2*c+1]) : a2[2*c+1];
                        w[c] = make_ulonglong2(p0, p1);
                    }
                    ulonglong2* wB = reinterpret_cast<ulonglong2*>(wbS + 144);
                    wB[0] = make_ulonglong2(rr2[0], rr2[1]);
                    wB[1] = make_ulonglong2(rr2[2], rr2[3]);
                    wB[2] = make_ulonglong2(rr2[4], rr2[5]);
                }
            }
        }

        // ---- zs in rr2 (scale by own dv); outputs are inner products
        {
            ull mv2 = pack2(mydv, mydv);
#pragma unroll
            for (int p = 0; p < 6; p++) rr2[p] = mul2(rr2[p], mv2);
        }
        float z[RPAD];
#pragma unroll
        for (int p = 0; p < 6; p++) unpack2(rr2[p], z[2*p], z[2*p+1]);

        float zKc = 0.f;
#pragma unroll
        for (int r = 0; r < RMAX; r++)
            if (r == nm) zKc = z[r];

        float pm[MM], sg[MM];
#pragma unroll
        for (int r = 0; r < MM; r++) { pm[r] = z[r] * zKc; sg[r] = z[r] * z[r]; }
        float vv = zKc * zKc;

#pragma unroll
        for (int off = 16; off > 0; off >>= 1) {
#pragma unroll
            for (int r = 0; r < MM; r++) {
                pm[r] += __shfl_xor_sync(0xffffffffu, pm[r], off);
                sg[r] += __shfl_xor_sync(0xffffffffu, sg[r], off);
            }
            vv += __shfl_xor_sync(0xffffffffu, vv, off);
        }
        {
            const int w = (tid >> 5) & 1, lane = tid & 31;
            if (lane == 0) {
#pragma unroll
                for (int r = 0; r < MM; r++) {
                    E->red[w][r]      = pm[r];
                    E->red[w][MM + r] = sg[r];
                }
                E->red[w][2 * MM] = vv;
            }
        }
        EBAR(barid);
        if (i == 0) {
            float var = 1.0f - (E->red[0][2*MM] + E->red[1][2*MM]);
            for (int r = 0; r < nm; r++) {
                int m = S->gmem[g][r];
                out[b * MM + m]              = E->red[0][r] + E->red[1][r];
                out[BATCH * MM + b * MM + m] = var;
                g_sig_partial[m * BATCH + b] = E->red[0][MM+r] + E->red[1][MM+r];
            }
        }
        EBAR(barid);
    }

    // ---- last-block sigma reduction (deterministic fixed-order sum)
    __threadfence();
    __syncthreads();
    if (tid == 0) S->ticket = atomicAdd(&g_done, 1u);
    __syncthreads();
    if (S->ticket == gridDim.x - 1) {
        __threadfence();
        const int lane = tid & 31, w = tid >> 5;
        for (int m = 0; m < MM; m++) {
            float s = 0.f;
            for (int t = tid; t < BATCH; t += 128)
                s += g_sig_partial[m * BATCH + t];
#pragma unroll
            for (int off = 16; off > 0; off >>= 1)
                s += __shfl_down_sync(0xffffffffu, s, off);
            if (lane == 0) S->sred[w] = s;
            __syncthreads();
            if (tid == 0) {
                float tot = S->sred[0] + S->sred[1] + S->sred[2] + S->sred[3];
                out[2 * BATCH * MM + m] = tot / (float)(BATCH * NNB);
            }
            __syncthreads();
        }
        if (tid == 0) g_done = 0;
    }
}

extern "C" void kernel_launch(void* const* d_in, const int* in_sizes, int n_in,
                              void* d_out, int out_size)
{
    const float* x    = (const float*)d_in[0];
    const float* ls   = (const float*)d_in[1];
    const float* eps  = (const float*)d_in[2];
    const int*   bidx = (const int*)d_in[3];
    const int*   nidx = (const int*)d_in[4];
    const float* Y    = (const float*)d_in[5];
    float* out = (float*)d_out;

    cudaFuncSetAttribute(muygps_main, cudaFuncAttributeMaxDynamicSharedMemorySize,
                         (int)sizeof(BlockSmem));
    muygps_main<<<BATCH / 2, 128, sizeof(BlockSmem)>>>(x, ls, eps, bidx, nidx, Y, out);
}

// round 12
// speedup vs baseline: 2.5828x; 1.0452x over previous
#include <cuda_runtime.h>

#define BATCH 2048
#define NNB   64
#define MM    10
#define FEAT  40
#define RMAX  (MM + 1)
#define RPAD  12
#define PDS   66            // spdA row stride: even (8B-packed) + conflict-free

typedef unsigned long long ull;

__device__ float g_sig_partial[MM * BATCH];
__device__ unsigned int g_done = 0;

#define EBAR(id)       asm volatile("bar.sync %0, 64;"   :: "r"(id) : "memory")
#define NBAR_SYNC(id)  asm volatile("bar.sync %0, 128;"  :: "r"(id) : "memory")
#define NBAR_ARRIVE(id) asm volatile("bar.arrive %0, 128;" :: "r"(id) : "memory")

__device__ __forceinline__ ull pack2(float lo, float hi) {
    ull r; asm("mov.b64 %0, {%1, %2};" : "=l"(r) : "f"(lo), "f"(hi)); return r;
}
__device__ __forceinline__ void unpack2(ull v, float& lo, float& hi) {
    asm("mov.b64 {%0, %1}, %2;" : "=f"(lo), "=f"(hi) : "l"(v));
}
__device__ __forceinline__ ull fma2(ull a, ull b, ull c) {
    ull r; asm("fma.rn.f32x2 %0, %1, %2, %3;" : "=l"(r) : "l"(a), "l"(b), "l"(c)); return r;
}
__device__ __forceinline__ ull add2(ull a, ull b) {
    ull r; asm("add.rn.f32x2 %0, %1, %2;" : "=l"(r) : "l"(a), "l"(b)); return r;
}
__device__ __forceinline__ ull mul2(ull a, ull b) {
    ull r; asm("mul.rn.f32x2 %0, %1, %2;" : "=l"(r) : "l"(a), "l"(b)); return r;
}

struct __align__(16) ElemSmem {
    float spdA[NNB][PDS];                // raw pairwise dots
    union {
        struct {                          // phase 1: transposed feature staging
            float sxnT[16][NNB];
            float sxb[16];
        } p1;
        struct {                          // phase 2: 3-deep publish ring
            float srow[3][176];           // [0..63] colA, [64..127] colB,
                                          // [128..139] rhsA, [144..155] rhsB, [160] dv2a
        } p2;
    } u;
    float snorm[NNB];
    int   sidx[NNB];
    float red[2][2 * MM + 1];
};

struct BlockSmem {
    ElemSmem e[2];
    float gls[MM], geps[MM];
    int   gcnt[MM];
    int   gmem[MM][MM];
    int   ng;
    unsigned int ticket;
    float sred[4];
};

__global__ void __launch_bounds__(128, 5)
muygps_main(const float* __restrict__ x,
            const float* __restrict__ ls,
            const float* __restrict__ eps,
            const int*   __restrict__ bidx,
            const int*   __restrict__ nidx,
            const float* __restrict__ Y,
            float*       __restrict__ out)
{
    extern __shared__ char smem_raw[];
    BlockSmem* S = reinterpret_cast<BlockSmem*>(smem_raw);
    const int tid = threadIdx.x;
    const int e   = tid >> 6;
    const int i   = tid & 63;
    const int idA = 1 + 2 * e;          // named barrier ids: {1,2} / {3,4}
    const int idB = 2 + 2 * e;
    const int b   = blockIdx.x * 2 + e;
    ElemSmem* E = &S->e[e];

    if (tid == 0) {
        int ng = 0;
        for (int m = 0; m < MM; m++) {
            float lm = ls[m], em = eps[m];
            int g = -1;
            for (int q = 0; q < ng; q++)
                if (S->gls[q] == lm && S->geps[q] == em) { g = q; break; }
            if (g < 0) { g = ng++; S->gls[g] = lm; S->geps[g] = em; S->gcnt[g] = 0; }
            S->gmem[g][S->gcnt[g]++] = m;
        }
        S->ng = ng;
    }

    const int myidx = nidx[b * NNB + i];
    const float* xrow = x + (size_t)myidx * FEAT;
    const float* xb   = x + (size_t)bidx[b] * FEAT;

    // ---- phase 1: 3 feature tiles (16,16,8); j-packed dots accumulate in spdA
    float nrm = 0.f, cd2 = 0.f;
#pragma unroll
    for (int t = 0; t < 3; t++) {
        const int f0  = (t == 0) ? 0 : (t == 1) ? 16 : 32;
        const int len = (t < 2) ? 16 : 8;
        ull xd[16];
        {
            const ulonglong2* xr = reinterpret_cast<const ulonglong2*>(xrow + f0);
#pragma unroll
            for (int q = 0; q < len / 4; q++) {
                ulonglong2 v = xr[q];
                float f0v, f1v, f2v, f3v;
                unpack2(v.x, f0v, f1v);
                unpack2(v.y, f2v, f3v);
                xd[4*q+0] = pack2(f0v, f0v);
                xd[4*q+1] = pack2(f1v, f1v);
                xd[4*q+2] = pack2(f2v, f2v);
                xd[4*q+3] = pack2(f3v, f3v);
                E->u.p1.sxnT[4*q+0][i] = f0v;
                E->u.p1.sxnT[4*q+1][i] = f1v;
                E->u.p1.sxnT[4*q+2][i] = f2v;
                E->u.p1.sxnT[4*q+3][i] = f3v;
                nrm += f0v*f0v + f1v*f1v;
                nrm += f2v*f2v + f3v*f3v;
            }
        }
        if (i < len) E->u.p1.sxb[i] = xb[f0 + i];
        if (t == 0)  E->sidx[i] = myidx;
        EBAR(idA);

#pragma unroll
        for (int f = 0; f < len; f++) {
            float lo, hi; unpack2(xd[f], lo, hi);
            float d = lo - E->u.p1.sxb[f];
            cd2 += d * d;
        }
        {
            const ulonglong2* colb = reinterpret_cast<const ulonglong2*>(&E->u.p1.sxnT[0][0]);
#pragma unroll 4
            for (int g4 = 0; g4 < 16; g4++) {
                ull acc0 = 0ull, acc1 = 0ull;
#pragma unroll
                for (int f = 0; f < len; f++) {
                    ulonglong2 v = colb[16 * f + g4];
                    acc0 = fma2(xd[f], v.x, acc0);
                    acc1 = fma2(xd[f], v.y, acc1);
                }
                ull* dst = reinterpret_cast<ull*>(&E->spdA[i][4 * g4]);
                if (t == 0) {
                    dst[0] = acc0;
                    dst[1] = acc1;
                } else {
                    dst[0] = add2(dst[0], acc0);
                    dst[1] = add2(dst[1], acc1);
                }
            }
        }
        EBAR(idA);
    }
    E->snorm[i] = nrm;
    const float cdist = (cd2 > 0.f) ? sqrtf(cd2) : 0.f;
    __syncthreads();       // snorm/sidx + group table visible; p1 reads done

    const float* Yrow = Y + ((size_t)b * NNB + i) * MM;
    const int ng = S->ng;

    for (int g = 0; g < ng; g++) {
        const float inv_ls = 1.0f / S->gls[g];
        const float epg    = S->geps[g];
        const int   nm     = S->gcnt[g];

        // ---- packed Kp row from raw dots
        ull a2[NNB / 2];
        {
            const float ni = nrm;
#pragma unroll
            for (int p = 0; p < NNB / 2; p++) {
                ull dot2 = *reinterpret_cast<const ull*>(&E->spdA[i][2 * p]);
                float d0, d1; unpack2(dot2, d0, d1);
                float n0 = E->snorm[2*p], n1 = E->snorm[2*p+1];
                float dd0 = ni + n0 - 2.f * d0;
                float dd1 = ni + n1 - 2.f * d1;
                if (E->sidx[2*p]   == myidx) dd0 = 0.f;
                if (E->sidx[2*p+1] == myidx) dd1 = 0.f;
                dd0 = (dd0 > 0.f) ? sqrtf(dd0) : 0.f;
                dd1 = (dd1 > 0.f) ? sqrtf(dd1) : 0.f;
                float e0 = __expf(-dd0 * inv_ls);
                float e1 = __expf(-dd1 * inv_ls);
                if (2*p   == i) e0 += epg;
                if (2*p+1 == i) e1 += epg;
                a2[p] = pack2(e0, e1);
            }
        }
        const float Kc = __expf(-cdist * inv_ls);

        // ---- packed rhs
        ull rr2[6];
        {
            float rv[RPAD];
#pragma unroll
            for (int r = 0; r < RPAD; r++) rv[r] = 0.f;
#pragma unroll
            for (int r = 0; r < MM; r++)
                if (r < nm) rv[r] = Yrow[S->gmem[g][r]];
#pragma unroll
            for (int r = 0; r < RMAX; r++)
                if (r == nm) rv[r] = Kc;
#pragma unroll
            for (int p = 0; p < 6; p++) rr2[p] = pack2(rv[2*p], rv[2*p+1]);
        }

        float mydv = 0.f;

        // ---- bootstrap: cooperative publish of cols 0/1 (pack 0) into ring buf 0
        {
            float* w0 = E->u.p2.srow[0];
            float lo0, hi0; unpack2(a2[0], lo0, hi0);
            w0[i]      = (i > 0) ? lo0 : 0.f;
            w0[64 + i] = (i > 0) ? hi0 : 0.f;   // diag of col 1 kept at i==1
            if (i == 0) {
                float dv = rsqrtf(lo0);
                mydv = dv;
                w0[160] = dv * dv;
                ulonglong2* wA = reinterpret_cast<ulonglong2*>(w0 + 128);
                wA[0] = make_ulonglong2(rr2[0], rr2[1]);
                wA[1] = make_ulonglong2(rr2[2], rr2[3]);
                wA[2] = make_ulonglong2(rr2[4], rr2[5]);
            }
            if (i == 1) {
                ulonglong2* wB = reinterpret_cast<ulonglong2*>(w0 + 144);
                wB[0] = make_ulonglong2(rr2[0], rr2[1]);
                wB[1] = make_ulonglong2(rr2[2], rr2[3]);
                wB[2] = make_ulonglong2(rr2[4], rr2[5]);
            }
            NBAR_ARRIVE(idA);   // T0 producer arrivals
        }

        // ---- double-step Cholesky + fused forward solve; early publish + tail
#pragma unroll
        for (int n = 0; n < 32; n++) {
            const int K = 2 * n;
            NBAR_SYNC((n & 1) ? idB : idA);
            const float* rbS = E->u.p2.srow[n % 3];
            float*       wbS = E->u.p2.srow[(n + 1) % 3];

            const float dv2a  = rbS[160];
            const float cak1  = rbS[K + 1];
            const float cbk1  = rbS[64 + K + 1];
            const float cc    = cak1 * dv2a;
            const float diagB = __fmaf_rn(-cc, cak1, cbk1);
            const float sdb   = rsqrtf(diagB);
            const float dv2b  = sdb * sdb;
            float aKlo, aKhi; unpack2(a2[n], aKlo, aKhi);
            const float t1 = aKlo * dv2a;
            const float t2 = __fmaf_rn(-t1, cak1, aKhi) * dv2b;
            const ull ncc2 = pack2(-cc, -cc);
            const ull nt12 = pack2(-t1, -t1);
            const ull nt22 = pack2(-t2, -t2);

            if (n < 31) {
                const int cp2 = n + 1;              // pack holding cols K+2,K+3
                float sA = 0.f, sB = 0.f;
                if (i > K + 1) {
                    ull vA = *reinterpret_cast<const ull*>(rbS + 2 * cp2);
                    ull vB = *reinterpret_cast<const ull*>(rbS + 64 + 2 * cp2);
                    ull bb = fma2(ncc2, vA, vB);
                    a2[cp2] = fma2(nt12, vA, a2[cp2]);
                    a2[cp2] = fma2(nt22, bb, a2[cp2]);
                    if (i > K + 2) unpack2(a2[cp2], sA, sB);   // keep diag at i==K+3
                }
                wbS[i]      = sA;
                wbS[64 + i] = sB;
                if (i == K + 2) {
                    float dlo, dhi_; unpack2(a2[cp2], dlo, dhi_);
                    float dv = rsqrtf(dlo);
                    mydv = dv;
                    wbS[160] = dv * dv;
                }
            }

            // rhs elimination
            if (i == K + 1) {
                mydv = sdb;
                const ulonglong2* rA = reinterpret_cast<const ulonglong2*>(rbS + 128);
#pragma unroll
                for (int c = 0; c < 3; c++) {
                    ulonglong2 v = rA[c];
                    rr2[2*c]   = fma2(nt12, v.x, rr2[2*c]);
                    rr2[2*c+1] = fma2(nt12, v.y, rr2[2*c+1]);
                }
            } else if (i > K + 1) {
                const ulonglong2* rA = reinterpret_cast<const ulonglong2*>(rbS + 128);
                const ulonglong2* rB = reinterpret_cast<const ulonglong2*>(rbS + 144);
#pragma unroll
                for (int c = 0; c < 3; c++) {
                    ulonglong2 vA = rA[c], vB = rB[c];
                    ull b0 = fma2(ncc2, vA.x, vB.x);
                    ull b1 = fma2(ncc2, vA.y, vB.y);
                    rr2[2*c]   = fma2(nt12, vA.x, rr2[2*c]);
                    rr2[2*c]   = fma2(nt22, b0,   rr2[2*c]);
                    rr2[2*c+1] = fma2(nt12, vA.y, rr2[2*c+1]);
                    rr2[2*c+1] = fma2(nt22, b1,   rr2[2*c+1]);
                }
            }

            if (n < 31) {
                if (i == K + 2) {
                    ulonglong2* wA = reinterpret_cast<ulonglong2*>(wbS + 128);
                    wA[0] = make_ulonglong2(rr2[0], rr2[1]);
                    wA[1] = make_ulonglong2(rr2[2], rr2[3]);
                    wA[2] = make_ulonglong2(rr2[4], rr2[5]);
                }
                if (i == K + 3) {
                    ulonglong2* wB = reinterpret_cast<ulonglong2*>(wbS + 144);
                    wB[0] = make_ulonglong2(rr2[0], rr2[1]);
                    wB[1] = make_ulonglong2(rr2[2], rr2[3]);
                    wB[2] = make_ulonglong2(rr2[4], rr2[5]);
                }
                NBAR_ARRIVE((n & 1) ? idA : idB);   // publish done; tail off-path

                // ---- tail: remaining packs (register-only; hidden in barrier slack)
                if (i > K + 1) {
                    const int pt0 = n + 2;           // first tail pack
                    if (pt0 & 1) {                   // odd pack boundary
                        if (pt0 < 32) {
                            ull vA = *reinterpret_cast<const ull*>(rbS + 2 * pt0);
                            ull vB = *reinterpret_cast<const ull*>(rbS + 64 + 2 * pt0);
                            ull bb = fma2(ncc2, vA, vB);
                            a2[pt0] = fma2(nt12, vA, a2[pt0]);
                            a2[pt0] = fma2(nt22, bb, a2[pt0]);
                        }
                    }
                    const int c0 = (pt0 + 1) >> 1;   // first full chunk (2 packs)
#pragma unroll
                    for (int c = c0; c < 16; c++) {
                        ulonglong2 vA2 = *reinterpret_cast<const ulonglong2*>(rbS + 4 * c);
                        ulonglong2 vB2 = *reinterpret_cast<const ulonglong2*>(rbS + 64 + 4 * c);
                        ull b0 = fma2(ncc2, vA2.x, vB2.x);
                        a2[2*c] = fma2(nt12, vA2.x, a2[2*c]);
                        a2[2*c] = fma2(nt22, b0,   a2[2*c]);
                        ull b1 = fma2(ncc2, vA2.y, vB2.y);
                        a2[2*c+1] = fma2(nt12, vA2.y, a2[2*c+1]);
                        a2[2*c+1] = fma2(nt22, b1,   a2[2*c+1]);
                    }
                }
            }
        }

        // ---- zs = D^{-1/2} L^{-1} rhs (scale by own dv); inner-product outputs
        {
            ull mv2 = pack2(mydv, mydv);
#pragma unroll
            for (int p = 0; p < 6; p++) rr2[p] = mul2(rr2[p], mv2);
        }
        float z[RPAD];
#pragma unroll
        for (int p = 0; p < 6; p++) unpack2(rr2[p], z[2*p], z[2*p+1]);

        float zKc = 0.f;
#pragma unroll
        for (int r = 0; r < RMAX; r++)
            if (r == nm) zKc = z[r];

        float pm[MM], sg[MM];
#pragma unroll
        for (int r = 0; r < MM; r++) { pm[r] = z[r] * zKc; sg[r] = z[r] * z[r]; }
        float vv = zKc * zKc;

#pragma unroll
        for (int off = 16; off > 0; off >>= 1) {
#pragma unroll
            for (int r = 0; r < MM; r++) {
                pm[r] += __shfl_xor_sync(0xffffffffu, pm[r], off);
                sg[r] += __shfl_xor_sync(0xffffffffu, sg[r], off);
            }
            vv += __shfl_xor_sync(0xffffffffu, vv, off);
        }
        {
            const int w = (tid >> 5) & 1, lane = tid & 31;
            if (lane == 0) {
#pragma unroll
                for (int r = 0; r < MM; r++) {
                    E->red[w][r]      = pm[r];
                    E->red[w][MM + r] = sg[r];
                }
                E->red[w][2 * MM] = vv;
            }
        }
        EBAR(idA);
        if (i == 0) {
            float var = 1.0f - (E->red[0][2*MM] + E->red[1][2*MM]);
            for (int r = 0; r < nm; r++) {
                int m = S->gmem[g][r];
                out[b * MM + m]              = E->red[0][r] + E->red[1][r];
                out[BATCH * MM + b * MM + m] = var;
                g_sig_partial[m * BATCH + b] = E->red[0][MM+r] + E->red[1][MM+r];
            }
        }
        EBAR(idA);
    }

    // ---- last-block sigma reduction (deterministic fixed-order sum)
    __threadfence();
    __syncthreads();
    if (tid == 0) S->ticket = atomicAdd(&g_done, 1u);
    __syncthreads();
    if (S->ticket == gridDim.x - 1) {
        __threadfence();
        const int lane = tid & 31, w = tid >> 5;
        for (int m = 0; m < MM; m++) {
            float s = 0.f;
            for (int t = tid; t < BATCH; t += 128)
                s += g_sig_partial[m * BATCH + t];
#pragma unroll
            for (int off = 16; off > 0; off >>= 1)
                s += __shfl_down_sync(0xffffffffu, s, off);
            if (lane == 0) S->sred[w] = s;
            __syncthreads();
            if (tid == 0) {
                float tot = S->sred[0] + S->sred[1] + S->sred[2] + S->sred[3];
                out[2 * BATCH * MM + m] = tot / (float)(BATCH * NNB);
            }
            __syncthreads();
        }
        if (tid == 0) g_done = 0;
    }
}

extern "C" void kernel_launch(void* const* d_in, const int* in_sizes, int n_in,
                              void* d_out, int out_size)
{
    const float* x    = (const float*)d_in[0];
    const float* ls   = (const float*)d_in[1];
    const float* eps  = (const float*)d_in[2];
    const int*   bidx = (const int*)d_in[3];
    const int*   nidx = (const int*)d_in[4];
    const float* Y    = (const float*)d_in[5];
    float* out = (float*)d_out;

    cudaFuncSetAttribute(muygps_main, cudaFuncAttributeMaxDynamicSharedMemorySize,
                         (int)sizeof(BlockSmem));
    muygps_main<<<BATCH / 2, 128, sizeof(BlockSmem)>>>(x, ls, eps, bidx, nidx, Y, out);
}